// round 12
// baseline (speedup 1.0000x reference)
#include <cuda_runtime.h>
#include <cuda_bf16.h>
#include <math.h>
#include <stdint.h>

#define S 4096
#define D 768
#define H 12
#define DH 64
#define L 12
#define FF 3072
#define W 256
#define OUT 256

// ---------------- scratch ----------------
__device__ float g_h[S * D];
__device__ float g_t[S * D];
__device__ __nv_bfloat16 g_qh[S * D], g_ql[S * D];
__device__ __nv_bfloat16 g_kh[S * D], g_kl[S * D];
__device__ __nv_bfloat16 g_vh[S * D], g_vl[S * D];
__device__ __nv_bfloat16 g_hh[S * D], g_hl[S * D];
__device__ __nv_bfloat16 g_ah[S * D], g_al[S * D];
__device__ __nv_bfloat16 g_fh[S * FF], g_fl[S * FF];
#define WT_PER_LAYER (4 * D * D + 2 * D * FF)
__device__ __nv_bfloat16 g_wTh[L * WT_PER_LAYER];
__device__ __nv_bfloat16 g_wTl[L * WT_PER_LAYER];

#define QSC 0.18033688011112042f

#define OQKV 0LL
#define OO (2304LL * 768)
#define OI (OO + 768LL * 768)
#define OD (OI + 3072LL * 768)

// ================= helpers =================
__device__ __forceinline__ uint32_t smem_u32(const void* p) {
    uint32_t a;
    asm("{ .reg .u64 t; cvta.to.shared.u64 t, %1; cvt.u32.u64 %0, t; }" : "=r"(a) : "l"(p));
    return a;
}
#define SWZ128(off) ((off) ^ (((off) >> 3) & 0x70))
#define SWZ64(off) ((off) ^ (((off) >> 3) & 0x30))

#define LDSM_X4(r, addr)                                                          \
    asm volatile("ldmatrix.sync.aligned.m8n8.x4.shared.b16 {%0,%1,%2,%3}, [%4];" \
                 : "=r"((r)[0]), "=r"((r)[1]), "=r"((r)[2]), "=r"((r)[3])         \
                 : "r"(addr))
#define LDSM_X4_T(r, addr)                                                              \
    asm volatile("ldmatrix.sync.aligned.m8n8.x4.trans.shared.b16 {%0,%1,%2,%3}, [%4];" \
                 : "=r"((r)[0]), "=r"((r)[1]), "=r"((r)[2]), "=r"((r)[3])               \
                 : "r"(addr))

#define MMA_BF16(d, a, b0, b1)                                                     \
    asm volatile(                                                                  \
        "mma.sync.aligned.m16n8k16.row.col.f32.bf16.bf16.f32 "                     \
        "{%0,%1,%2,%3}, {%4,%5,%6,%7}, {%8,%9}, {%0,%1,%2,%3};"                    \
        : "+f"((d)[0]), "+f"((d)[1]), "+f"((d)[2]), "+f"((d)[3])                   \
        : "r"((a)[0]), "r"((a)[1]), "r"((a)[2]), "r"((a)[3]), "r"(b0), "r"(b1))

#define CP_ASYNC16(dst, src) \
    asm volatile("cp.async.cg.shared.global [%0], [%1], 16;" ::"r"(dst), "l"(src))
#define CP_ASYNC16Z(dst, src, sz) \
    asm volatile("cp.async.cg.shared.global [%0], [%1], 16, %2;" ::"r"(dst), "l"(src), "r"(sz))
#define CP_COMMIT asm volatile("cp.async.commit_group;" ::: "memory")
#define CP_WAIT(n) asm volatile("cp.async.wait_group %0;" ::"n"(n) : "memory")

__device__ __forceinline__ void split_pair(float u0, float u1, __nv_bfloat16* ph,
                                           __nv_bfloat16* pl) {
    __nv_bfloat16 h0 = __float2bfloat16_rn(u0);
    __nv_bfloat16 h1 = __float2bfloat16_rn(u1);
    __nv_bfloat16 l0 = __float2bfloat16_rn(u0 - __bfloat162float(h0));
    __nv_bfloat16 l1 = __float2bfloat16_rn(u1 - __bfloat162float(h1));
    uint32_t hp = ((uint32_t)__bfloat16_as_ushort(h1) << 16) | __bfloat16_as_ushort(h0);
    uint32_t lp = ((uint32_t)__bfloat16_as_ushort(l1) << 16) | __bfloat16_as_ushort(l0);
    *(uint32_t*)ph = hp;
    *(uint32_t*)pl = lp;
}
__device__ __forceinline__ void pack_hl(float a, float b, uint32_t& hi, uint32_t& lo) {
    __nv_bfloat16 ha = __float2bfloat16_rn(a);
    __nv_bfloat16 hb = __float2bfloat16_rn(b);
    __nv_bfloat16 la = __float2bfloat16_rn(a - __bfloat162float(ha));
    __nv_bfloat16 lb = __float2bfloat16_rn(b - __bfloat162float(hb));
    hi = ((uint32_t)__bfloat16_as_ushort(hb) << 16) | __bfloat16_as_ushort(ha);
    lo = ((uint32_t)__bfloat16_as_ushort(lb) << 16) | __bfloat16_as_ushort(la);
}

// ================= small kernels =================
__device__ __forceinline__ float block_sum_256(float v) {
    __shared__ float red[8];
    int lane = threadIdx.x & 31, wid = threadIdx.x >> 5;
#pragma unroll
    for (int o = 16; o > 0; o >>= 1) v += __shfl_down_sync(0xffffffffu, v, o);
    if (lane == 0) red[wid] = v;
    __syncthreads();
    if (wid == 0) {
        v = (lane < 8) ? red[lane] : 0.0f;
#pragma unroll
        for (int o = 4; o > 0; o >>= 1) v += __shfl_down_sync(0xffffffffu, v, o);
        if (lane == 0) red[0] = v;
    }
    __syncthreads();
    v = red[0];
    __syncthreads();
    return v;
}

__global__ void emb_kernel(const int* __restrict__ x, const float* __restrict__ we,
                           const float* __restrict__ pe, const float* __restrict__ tt,
                           float* __restrict__ out) {
    int s = blockIdx.x;
    int w = x[s];
    const float* wrow = we + (long long)w * D;
    const float* prow = pe + (long long)(s + 2) * D;
    for (int d = threadIdx.x; d < D; d += 256)
        out[s * D + d] = wrow[d] + prow[d] + tt[d];
}

__global__ void ln_kernel(const float* __restrict__ in, const float* __restrict__ g,
                          const float* __restrict__ b, float* __restrict__ out,
                          __nv_bfloat16* __restrict__ outh, __nv_bfloat16* __restrict__ outl) {
    int row = blockIdx.x;
    const float* x = in + row * D;
    float lsum = 0.0f;
    for (int d = threadIdx.x; d < D; d += 256) lsum += x[d];
    float mu = block_sum_256(lsum) * (1.0f / D);
    float lvar = 0.0f;
    for (int d = threadIdx.x; d < D; d += 256) {
        float t = x[d] - mu;
        lvar += t * t;
    }
    float var = block_sum_256(lvar) * (1.0f / D);
    float inv = rsqrtf(var + 1e-5f);
    for (int d = threadIdx.x; d < D; d += 256) {
        float y = (x[d] - mu) * inv * g[d] + b[d];
        out[row * D + d] = y;
        __nv_bfloat16 hv = __float2bfloat16_rn(y);
        outh[row * D + d] = hv;
        outl[row * D + d] = __float2bfloat16_rn(y - __bfloat162float(hv));
    }
}

// ---- batched transpose+split ----
__device__ __forceinline__ void tsp_body(const float* __restrict__ in,
                                         __nv_bfloat16* __restrict__ outh,
                                         __nv_bfloat16* __restrict__ outl, int R, int Ccols) {
    __shared__ float tile[32][33];
    int c0 = blockIdx.x * 32, r0 = blockIdx.y * 32;
    for (int i = threadIdx.y; i < 32; i += 8)
        tile[i][threadIdx.x] = in[(long long)(r0 + i) * Ccols + c0 + threadIdx.x];
    __syncthreads();
    for (int i = threadIdx.y; i < 32; i += 8) {
        float v = tile[threadIdx.x][i];
        __nv_bfloat16 hv = __float2bfloat16_rn(v);
        __nv_bfloat16 lv = __float2bfloat16_rn(v - __bfloat162float(hv));
        long long o = (long long)(c0 + i) * R + r0 + threadIdx.x;
        outh[o] = hv;
        outl[o] = lv;
    }
}
__global__ void tsp_dd(const float* __restrict__ Wq, const float* __restrict__ Wk,
                       const float* __restrict__ Wv, const float* __restrict__ Wo,
                       __nv_bfloat16* __restrict__ wTh, __nv_bfloat16* __restrict__ wTl) {
    int l = blockIdx.z >> 2, m = blockIdx.z & 3;
    const float* src = (m == 0 ? Wq : m == 1 ? Wk : m == 2 ? Wv : Wo) + (long long)l * D * D;
    long long dst = (long long)l * WT_PER_LAYER + (m < 3 ? OQKV + (long long)m * D * D : OO);
    tsp_body(src, wTh + dst, wTl + dst, D, D);
}
__global__ void tsp_wi(const float* __restrict__ Wi, __nv_bfloat16* __restrict__ wTh,
                       __nv_bfloat16* __restrict__ wTl) {
    int l = blockIdx.z;
    long long dst = (long long)l * WT_PER_LAYER + OI;
    tsp_body(Wi + (long long)l * D * FF, wTh + dst, wTl + dst, D, FF);
}
__global__ void tsp_wd(const float* __restrict__ Wd, __nv_bfloat16* __restrict__ wTh,
                       __nv_bfloat16* __restrict__ wTl) {
    int l = blockIdx.z;
    long long dst = (long long)l * WT_PER_LAYER + OD;
    tsp_body(Wd + (long long)l * FF * D, wTh + dst, wTl + dst, FF, D);
}

// ===== bf16x3 GEMM: 128x128 tile, warp 64x32, BK=32, 2-stage single-sync, 2 CTAs/SM =====
// Stage (32KB): AH[0,8K) AL[8K,16K) BH[16K,24K) BL[24K,32K); rows 64B, SW64 swizzle.
#define BM 128
#define BN 128
#define BK 32
#define GA_AL 8192
#define GA_BH 16384
#define GA_BL 24576
#define GSTG 32768
#define SMEM_G (2 * GSTG)

// EPI: 0 = bias -> qkv planes (Q scaled); 1 = bias+gelu -> planes; 2 = bias+resid -> fp32
template <int EPI>
__global__ __launch_bounds__(256, 2) void mgemm128(
    const __nv_bfloat16* __restrict__ Ah_g, const __nv_bfloat16* __restrict__ Al_g,
    const __nv_bfloat16* __restrict__ Bh_g, const __nv_bfloat16* __restrict__ Bl_g,
    const float* __restrict__ b0, const float* __restrict__ b1, const float* __restrict__ b2,
    const float* __restrict__ resid, float* __restrict__ C0,
    __nv_bfloat16* __restrict__ P0h, __nv_bfloat16* __restrict__ P0l,
    __nv_bfloat16* __restrict__ P1h, __nv_bfloat16* __restrict__ P1l,
    __nv_bfloat16* __restrict__ P2h, __nv_bfloat16* __restrict__ P2l, int Nst, int K) {
    extern __shared__ char smem[];
    uint32_t sb = smem_u32(smem);
    int tid = threadIdx.x;
    int lane = tid & 31;
    int wid = tid >> 5;
    int wm = wid >> 2;  // 0..1 -> 64 rows each
    int wn = wid & 3;   // 0..3 -> 32 cols each
    int m0 = blockIdx.y * BM;
    int n0 = blockIdx.x * BN;

    const char* Ahb = (const char*)Ah_g + ((long long)m0 * K) * 2;
    const char* Alb = (const char*)Al_g + ((long long)m0 * K) * 2;
    const char* Bhb = (const char*)Bh_g + ((long long)n0 * K) * 2;
    const char* Blb = (const char*)Bl_g + ((long long)n0 * K) * 2;
    const long long rowstride = (long long)K * 2;

    float acc[4][4][4];
#pragma unroll
    for (int i = 0; i < 4; i++)
#pragma unroll
        for (int j = 0; j < 4; j++)
#pragma unroll
            for (int r = 0; r < 4; r++) acc[i][j][r] = 0.0f;

    const int lrow = lane & 15;
    const int lhalf = lane >> 4;
    const int T = K / BK;

    // A/B planes: 8KB = 512 16B-chunks -> 2 per thread each; 64B rows.
    int rowa[2], cba[2];
    uint32_t offa[2];
#pragma unroll
    for (int i = 0; i < 2; i++) {
        int ck = i * 256 + tid;
        rowa[i] = ck >> 2;
        cba[i] = (ck & 3) * 16;
        offa[i] = SWZ64((uint32_t)(rowa[i] * 64 + cba[i]));
    }

#define LOAD_STAGE(t, s)                                                \
    do {                                                                \
        uint32_t stg = sb + (s) * GSTG;                                 \
        long long kb = (long long)(t) * (BK * 2);                       \
        _Pragma("unroll") for (int i = 0; i < 2; i++) {                 \
            long long src = rowa[i] * rowstride + kb + cba[i];          \
            CP_ASYNC16(stg + offa[i], Ahb + src);                       \
            CP_ASYNC16(stg + GA_AL + offa[i], Alb + src);               \
            CP_ASYNC16(stg + GA_BH + offa[i], Bhb + src);               \
            CP_ASYNC16(stg + GA_BL + offa[i], Blb + src);               \
        }                                                               \
    } while (0)

    LOAD_STAGE(0, 0);
    CP_COMMIT;

    for (int t = 0; t < T; t++) {
        CP_WAIT(0);
        __syncthreads();
        if (t + 1 < T) {
            LOAD_STAGE(t + 1, (t + 1) & 1);
            CP_COMMIT;
        }
        uint32_t stg = sb + (t & 1) * GSTG;
#pragma unroll
        for (int ks = 0; ks < 2; ks++) {
            int kb = ks * 32 + lhalf * 16;
            // B fragments once per k16 (warp covers 32 cols -> 2 g2 frags per plane)
            uint32_t bh[2][4], bl[2][4];
#pragma unroll
            for (int g2 = 0; g2 < 2; g2++) {
                int r = wn * 32 + g2 * 16 + lrow;
                uint32_t off = SWZ64((uint32_t)(r * 64 + kb));
                LDSM_X4(bh[g2], stg + GA_BH + off);
                LDSM_X4(bl[g2], stg + GA_BL + off);
            }
            // A fragments per mt (keeps register pressure low)
#pragma unroll
            for (int mt = 0; mt < 4; mt++) {
                uint32_t ah[4], al[4];
                int r = wm * 64 + mt * 16 + lrow;
                uint32_t off = SWZ64((uint32_t)(r * 64 + kb));
                LDSM_X4(ah, stg + off);
                LDSM_X4(al, stg + GA_AL + off);
#pragma unroll
                for (int j = 0; j < 4; j++) {
                    uint32_t b0h = bh[j >> 1][j & 1], b1h = bh[j >> 1][(j & 1) + 2];
                    uint32_t b0l = bl[j >> 1][j & 1], b1l = bl[j >> 1][(j & 1) + 2];
                    MMA_BF16(acc[mt][j], ah, b0h, b1h);
                    MMA_BF16(acc[mt][j], ah, b0l, b1l);
                    MMA_BF16(acc[mt][j], al, b0h, b1h);
                }
            }
        }
    }

    // ---- epilogue ----
    int g = lane >> 2;
    int tig = lane & 3;

    const float* bias = b0;
    __nv_bfloat16 *Poh = P0h, *Pol = P0l;
    int ncol0 = n0;
    int mat = 0;
    if (EPI == 0) {
        mat = n0 / 768;
        ncol0 = n0 % 768;
        bias = (mat == 0) ? b0 : ((mat == 1) ? b1 : b2);
        Poh = (mat == 0) ? P0h : ((mat == 1) ? P1h : P2h);
        Pol = (mat == 0) ? P0l : ((mat == 1) ? P1l : P2l);
    }
    const int ost = (EPI == 0) ? 768 : Nst;

#pragma unroll
    for (int mt = 0; mt < 4; mt++) {
#pragma unroll
        for (int j = 0; j < 4; j++) {
            int colrel = ncol0 + wn * 32 + j * 8 + tig * 2;
            float bia0 = bias[colrel], bia1 = bias[colrel + 1];
#pragma unroll
            for (int half = 0; half < 2; half++) {
                int row = m0 + wm * 64 + mt * 16 + g + half * 8;
                long long rb = (long long)row * ost + colrel;
                float u0 = acc[mt][j][half * 2 + 0] + bia0;
                float u1 = acc[mt][j][half * 2 + 1] + bia1;
                if (EPI == 0) {
                    if (mat == 0) {
                        u0 *= QSC;
                        u1 *= QSC;
                    }
                    split_pair(u0, u1, Poh + rb, Pol + rb);
                } else if (EPI == 1) {
                    u0 = 0.5f * u0 * (1.0f + erff(u0 * 0.70710678118654752f));
                    u1 = 0.5f * u1 * (1.0f + erff(u1 * 0.70710678118654752f));
                    split_pair(u0, u1, Poh + rb, Pol + rb);
                } else {
                    u0 += resid[rb];
                    u1 += resid[rb + 1];
                    *(float2*)(&C0[rb]) = make_float2(u0, u1);
                }
            }
        }
    }
}

// ================= tensor-core sliding-window attention =================
#define AQR 128
#define AKT 64
#define ANT 10
#define AST_BASE 32768
#define ATT_SMEM (32768 + 2 * 32768)

__global__ __launch_bounds__(256, 2) void attn_tc(
    const __nv_bfloat16* __restrict__ qh, const __nv_bfloat16* __restrict__ ql,
    const __nv_bfloat16* __restrict__ kh, const __nv_bfloat16* __restrict__ kl,
    const __nv_bfloat16* __restrict__ vh, const __nv_bfloat16* __restrict__ vl,
    __nv_bfloat16* __restrict__ aoh, __nv_bfloat16* __restrict__ aol) {
    extern __shared__ char smem[];
    uint32_t sb = smem_u32(smem);
    int tid = threadIdx.x;
    int lane = tid & 31;
    int wid = tid >> 5;
    int c = blockIdx.x;
    int h = blockIdx.y;
    const int q0g = c * AQR;
    const int cbase = q0g - W;
    const int lrow = lane & 15;
    const int lhalf = lane >> 4;
    const int wr0 = wid * 16;

#pragma unroll
    for (int i = 0; i < 4; i++) {
        int id = i * 256 + tid;
        int row = id >> 3;
        int cb = (id & 7) * 16;
        long long gsrc = ((long long)(q0g + row) * D + h * DH) * 2 + cb;
        uint32_t dst = sb + SWZ128((uint32_t)(row * 128 + cb));
        CP_ASYNC16(dst, (const char*)qh + gsrc);
        CP_ASYNC16(dst + 16384, (const char*)ql + gsrc);
    }

#define ATT_LOAD(kt, s)                                                               \
    do {                                                                              \
        uint32_t stb = sb + AST_BASE + (s) * 32768;                                   \
        _Pragma("unroll") for (int pl_ = 0; pl_ < 4; pl_++) {                         \
            const char* gp = (pl_ == 0)   ? (const char*)kh                           \
                             : (pl_ == 1) ? (const char*)kl                           \
                             : (pl_ == 2) ? (const char*)vh                           \
                                          : (const char*)vl;                          \
            _Pragma("unroll") for (int j_ = 0; j_ < 2; j_++) {                        \
                int rem = j_ * 256 + tid;                                             \
                int row = rem >> 3;                                                   \
                int cb = (rem & 7) * 16;                                              \
                int kg = cbase + (kt) * AKT + row;                                    \
                int ok = (kg >= 0 && kg < S);                                         \
                int kgc = ok ? kg : 0;                                                \
                long long gsrc = ((long long)kgc * D + h * DH) * 2 + cb;              \
                CP_ASYNC16Z(stb + pl_ * 8192 + SWZ128((uint32_t)(row * 128 + cb)),    \
                            gp + gsrc, ok ? 16 : 0);                                  \
            }                                                                         \
        }                                                                             \
    } while (0)

    ATT_LOAD(0, 0);
    CP_COMMIT;

    float acc[8][4];
#pragma unroll
    for (int nf = 0; nf < 8; nf++)
#pragma unroll
        for (int e = 0; e < 4; e++) acc[nf][e] = 0.0f;
    float mrow[2] = {-1e30f, -1e30f};
    float lrowv[2] = {0.0f, 0.0f};

    for (int kt = 0; kt < ANT; kt++) {
        CP_WAIT(0);
        __syncthreads();
        if (kt + 1 < ANT) {
            ATT_LOAD(kt + 1, (kt + 1) & 1);
            CP_COMMIT;
        }
        int jg0 = kt * AKT;
        bool active = (jg0 + AKT > wr0) && (jg0 <= wr0 + 15 + 2 * W);
        if (active) {
            uint32_t stb = sb + AST_BASE + (kt & 1) * 32768;
            uint32_t KH = stb, KL = stb + 8192, VH = stb + 16384, VL = stb + 24576;

            float sf[8][4];
#pragma unroll
            for (int nf = 0; nf < 8; nf++)
#pragma unroll
                for (int e = 0; e < 4; e++) sf[nf][e] = 0.0f;

#pragma unroll
            for (int ks = 0; ks < 4; ks++) {
                int kb = ks * 32 + lhalf * 16;
                uint32_t qhf[4], qlf[4];
                uint32_t qoff = SWZ128((uint32_t)((wr0 + lrow) * 128 + kb));
                LDSM_X4(qhf, sb + qoff);
                LDSM_X4(qlf, sb + 16384 + qoff);
#pragma unroll
                for (int nf2 = 0; nf2 < 4; nf2++) {
                    uint32_t khf[4], klf[4];
                    uint32_t off = SWZ128((uint32_t)((nf2 * 16 + lrow) * 128 + kb));
                    LDSM_X4(khf, KH + off);
                    LDSM_X4(klf, KL + off);
#pragma unroll
                    for (int hf = 0; hf < 2; hf++) {
                        int nf = nf2 * 2 + hf;
                        uint32_t b0h = khf[hf], b1h = khf[hf + 2];
                        uint32_t b0l = klf[hf], b1l = klf[hf + 2];
                        MMA_BF16(sf[nf], qhf, b0h, b1h);
                        MMA_BF16(sf[nf], qhf, b0l, b1l);
                        MMA_BF16(sf[nf], qlf, b0h, b1h);
                    }
                }
            }

            int rA = wr0 + (lane >> 2);
            int rB = rA + 8;
#pragma unroll
            for (int nf = 0; nf < 8; nf++)
#pragma unroll
                for (int e = 0; e < 4; e++) {
                    int col = jg0 + nf * 8 + (lane & 3) * 2 + (e & 1);
                    int row = (e < 2) ? rA : rB;
                    int kg = cbase + col;
                    bool ok = (col >= row) && (col <= row + 2 * W) && (kg >= 0) && (kg < S);
                    if (!ok) sf[nf][e] = -1e30f;
                }
            float mA = -1e30f, mB = -1e30f;
#pragma unroll
            for (int nf = 0; nf < 8; nf++) {
                mA = fmaxf(mA, fmaxf(sf[nf][0], sf[nf][1]));
                mB = fmaxf(mB, fmaxf(sf[nf][2], sf[nf][3]));
            }
            mA = fmaxf(mA, __shfl_xor_sync(0xffffffffu, mA, 1));
            mA = fmaxf(mA, __shfl_xor_sync(0xffffffffu, mA, 2));
            mB = fmaxf(mB, __shfl_xor_sync(0xffffffffu, mB, 1));
            mB = fmaxf(mB, __shfl_xor_sync(0xffffffffu, mB, 2));
            float mnA = fmaxf(mrow[0], mA);
            float mnB = fmaxf(mrow[1], mB);
            float scA = exp2f(mrow[0] - mnA);
            float scB = exp2f(mrow[1] - mnB);
            float sumA = 0.0f, sumB = 0.0f;
#pragma unroll
            for (int nf = 0; nf < 8; nf++) {
                float p0 = exp2f(sf[nf][0] - mnA);
                float p1 = exp2f(sf[nf][1] - mnA);
                float p2 = exp2f(sf[nf][2] - mnB);
                float p3 = exp2f(sf[nf][3] - mnB);
                sf[nf][0] = p0;
                sf[nf][1] = p1;
                sf[nf][2] = p2;
                sf[nf][3] = p3;
                sumA += p0 + p1;
                sumB += p2 + p3;
            }
            sumA += __shfl_xor_sync(0xffffffffu, sumA, 1);
            sumA += __shfl_xor_sync(0xffffffffu, sumA, 2);
            sumB += __shfl_xor_sync(0xffffffffu, sumB, 1);
            sumB += __shfl_xor_sync(0xffffffffu, sumB, 2);
            lrowv[0] = lrowv[0] * scA + sumA;
            lrowv[1] = lrowv[1] * scB + sumB;
#pragma unroll
            for (int of = 0; of < 8; of++) {
                acc[of][0] *= scA;
                acc[of][1] *= scA;
                acc[of][2] *= scB;
                acc[of][3] *= scB;
            }
            mrow[0] = mnA;
            mrow[1] = mnB;

#pragma unroll
            for (int ks2 = 0; ks2 < 4; ks2++) {
                const float* s0 = sf[2 * ks2];
                const float* s1 = sf[2 * ks2 + 1];
                uint32_t pah[4], pal[4];
                pack_hl(s0[0], s0[1], pah[0], pal[0]);
                pack_hl(s0[2], s0[3], pah[1], pal[1]);
                pack_hl(s1[0], s1[1], pah[2], pal[2]);
                pack_hl(s1[2], s1[3], pah[3], pal[3]);
#pragma unroll
                for (int vf2 = 0; vf2 < 4; vf2++) {
                    uint32_t vhf[4], vlf[4];
                    uint32_t off =
                        SWZ128((uint32_t)((ks2 * 16 + lrow) * 128 + vf2 * 32 + lhalf * 16));
                    LDSM_X4_T(vhf, VH + off);
                    LDSM_X4_T(vlf, VL + off);
#pragma unroll
                    for (int hf = 0; hf < 2; hf++) {
                        int nf = vf2 * 2 + hf;
                        uint32_t b0h = vhf[hf * 2], b1h = vhf[hf * 2 + 1];
                        uint32_t b0l = vlf[hf * 2], b1l = vlf[hf * 2 + 1];
                        MMA_BF16(acc[nf], pah, b0h, b1h);
                        MMA_BF16(acc[nf], pah, b0l, b1l);
                        MMA_BF16(acc[nf], pal, b0h, b1h);
                    }
                }
            }
        }
    }

    {
        float invA = 1.0f / lrowv[0];
        float invB = 1.0f / lrowv[1];
        int rA = wr0 + (lane >> 2);
        long long baseA = (long long)(q0g + rA) * D + h * DH;
        long long baseB = baseA + 8LL * D;
#pragma unroll
        for (int nf = 0; nf < 8; nf++) {
            int col = nf * 8 + (lane & 3) * 2;
            split_pair(acc[nf][0] * invA, acc[nf][1] * invA, aoh + baseA + col,
                       aol + baseA + col);
            split_pair(acc[nf][2] * invB, acc[nf][3] * invB, aoh + baseB + col,
                       aol + baseB + col);
        }
    }
}

__global__ void head_kernel(const float* __restrict__ hrow, const float* __restrict__ w,
                            const float* __restrict__ b, float* __restrict__ out) {
    int o = threadIdx.x;
    float acc = b[o];
    for (int d = 0; d < D; d++) acc += hrow[d] * w[d * OUT + o];
    out[o] = acc;
}

// ================= launch =================
extern "C" void kernel_launch(void* const* d_in, const int* in_sizes, int n_in,
                              void* d_out, int out_size) {
    (void)in_sizes; (void)n_in; (void)out_size;
    const int* x = (const int*)d_in[0];
    const float* word_emb = (const float*)d_in[1];
    const float* pos_emb = (const float*)d_in[2];
    const float* tt_emb = (const float*)d_in[3];
    const float* elg = (const float*)d_in[4];
    const float* elb = (const float*)d_in[5];
    const float* Wq = (const float*)d_in[6];
    const float* bq = (const float*)d_in[7];
    const float* Wk = (const float*)d_in[8];
    const float* bk = (const float*)d_in[9];
    const float* Wv = (const float*)d_in[10];
    const float* bv = (const float*)d_in[11];
    const float* Wo = (const float*)d_in[12];
    const float* bo = (const float*)d_in[13];
    const float* g1 = (const float*)d_in[14];
    const float* b1 = (const float*)d_in[15];
    const float* Wi = (const float*)d_in[16];
    const float* bi = (const float*)d_in[17];
    const float* Wd = (const float*)d_in[18];
    const float* bd = (const float*)d_in[19];
    const float* g2 = (const float*)d_in[20];
    const float* b2 = (const float*)d_in[21];
    const float* ow = (const float*)d_in[22];
    const float* ob = (const float*)d_in[23];
    float* out = (float*)d_out;

    float *h, *t;
    __nv_bfloat16 *qh, *ql, *kh, *kl, *vh, *vl, *hh, *hl, *ah, *al, *fh, *fl, *wTh, *wTl;
    cudaGetSymbolAddress((void**)&h, g_h);
    cudaGetSymbolAddress((void**)&t, g_t);
    cudaGetSymbolAddress((void**)&qh, g_qh);
    cudaGetSymbolAddress((void**)&ql, g_ql);
    cudaGetSymbolAddress((void**)&kh, g_kh);
    cudaGetSymbolAddress((void**)&kl, g_kl);
    cudaGetSymbolAddress((void**)&vh, g_vh);
    cudaGetSymbolAddress((void**)&vl, g_vl);
    cudaGetSymbolAddress((void**)&hh, g_hh);
    cudaGetSymbolAddress((void**)&hl, g_hl);
    cudaGetSymbolAddress((void**)&ah, g_ah);
    cudaGetSymbolAddress((void**)&al, g_al);
    cudaGetSymbolAddress((void**)&fh, g_fh);
    cudaGetSymbolAddress((void**)&fl, g_fl);
    cudaGetSymbolAddress((void**)&wTh, g_wTh);
    cudaGetSymbolAddress((void**)&wTl, g_wTl);

    cudaFuncSetAttribute(mgemm128<0>, cudaFuncAttributeMaxDynamicSharedMemorySize, SMEM_G);
    cudaFuncSetAttribute(mgemm128<1>, cudaFuncAttributeMaxDynamicSharedMemorySize, SMEM_G);
    cudaFuncSetAttribute(mgemm128<2>, cudaFuncAttributeMaxDynamicSharedMemorySize, SMEM_G);
    cudaFuncSetAttribute(attn_tc, cudaFuncAttributeMaxDynamicSharedMemorySize, ATT_SMEM);

    dim3 tb(32, 8);
    tsp_dd<<<dim3(D / 32, D / 32, 4 * L), tb>>>(Wq, Wk, Wv, Wo, wTh, wTl);
    emb_kernel<<<S, 256>>>(x, word_emb, pos_emb, tt_emb, t);
    ln_kernel<<<S, 256>>>(t, elg, elb, h, hh, hl);

    dim3 gqkv(2304 / BN, S / BM);  // 18 x 32
    dim3 gproj(768 / BN, S / BM);  // 6 x 32
    dim3 gff1(FF / BN, S / BM);    // 24 x 32
    dim3 gattn(S / AQR, H);        // 32 x 12

    for (int l = 0; l < L; l++) {
        long long lb = (long long)l * WT_PER_LAYER;

        mgemm128<0><<<gqkv, 256, SMEM_G>>>(hh, hl, wTh + lb + OQKV, wTl + lb + OQKV,
                                           bq + l * D, bk + l * D, bv + l * D, nullptr,
                                           nullptr, qh, ql, kh, kl, vh, vl, 768, D);

        if (l == 0) {
            tsp_wi<<<dim3(FF / 32, D / 32, L), tb>>>(Wi, wTh, wTl);
            tsp_wd<<<dim3(D / 32, FF / 32, L), tb>>>(Wd, wTh, wTl);
        }

        attn_tc<<<gattn, 256, ATT_SMEM>>>(qh, ql, kh, kl, vh, vl, ah, al);

        mgemm128<2><<<gproj, 256, SMEM_G>>>(ah, al, wTh + lb + OO, wTl + lb + OO,
                                            bo + l * D, nullptr, nullptr, h, t,
                                            nullptr, nullptr, nullptr, nullptr, nullptr,
                                            nullptr, 768, D);
        ln_kernel<<<S, 256>>>(t, g1 + l * D, b1 + l * D, h, hh, hl);

        mgemm128<1><<<gff1, 256, SMEM_G>>>(hh, hl, wTh + lb + OI, wTl + lb + OI,
                                           bi + l * FF, nullptr, nullptr, nullptr, nullptr,
                                           fh, fl, nullptr, nullptr, nullptr, nullptr, FF, D);
        mgemm128<2><<<gproj, 256, SMEM_G>>>(fh, fl, wTh + lb + OD, wTl + lb + OD,
                                            bd + l * D, nullptr, nullptr, h, t,
                                            nullptr, nullptr, nullptr, nullptr, nullptr,
                                            nullptr, 768, FF);
        ln_kernel<<<S, 256>>>(t, g2 + l * D, b2 + l * D, h, hh, hl);
    }

    head_kernel<<<1, 256>>>(h, ow, ob, out);
}

// round 13
// speedup vs baseline: 1.2531x; 1.2531x over previous
#include <cuda_runtime.h>
#include <cuda_bf16.h>
#include <math.h>
#include <stdint.h>

#define S 4096
#define D 768
#define H 12
#define DH 64
#define L 12
#define FF 3072
#define W 256
#define OUT 256

// ---------------- scratch ----------------
__device__ float g_h[S * D];
__device__ float g_t[S * D];
__device__ float g_part[4 * S * D];  // split-K partials for FF2
__device__ __nv_bfloat16 g_qh[S * D], g_ql[S * D];
__device__ __nv_bfloat16 g_kh[S * D], g_kl[S * D];
__device__ __nv_bfloat16 g_vh[S * D], g_vl[S * D];
__device__ __nv_bfloat16 g_hh[S * D], g_hl[S * D];
__device__ __nv_bfloat16 g_ah[S * D], g_al[S * D];
__device__ __nv_bfloat16 g_fh[S * FF], g_fl[S * FF];
#define WT_PER_LAYER (4 * D * D + 2 * D * FF)
__device__ __nv_bfloat16 g_wTh[L * WT_PER_LAYER];
__device__ __nv_bfloat16 g_wTl[L * WT_PER_LAYER];

#define QSC 0.18033688011112042f

#define OQKV 0LL
#define OO (2304LL * 768)
#define OI (OO + 768LL * 768)
#define OD (OI + 3072LL * 768)

// ================= helpers =================
__device__ __forceinline__ uint32_t smem_u32(const void* p) {
    uint32_t a;
    asm("{ .reg .u64 t; cvta.to.shared.u64 t, %1; cvt.u32.u64 %0, t; }" : "=r"(a) : "l"(p));
    return a;
}
#define SWZ128(off) ((off) ^ (((off) >> 3) & 0x70))

#define LDSM_X4(r, addr)                                                          \
    asm volatile("ldmatrix.sync.aligned.m8n8.x4.shared.b16 {%0,%1,%2,%3}, [%4];" \
                 : "=r"((r)[0]), "=r"((r)[1]), "=r"((r)[2]), "=r"((r)[3])         \
                 : "r"(addr))
#define LDSM_X4_T(r, addr)                                                              \
    asm volatile("ldmatrix.sync.aligned.m8n8.x4.trans.shared.b16 {%0,%1,%2,%3}, [%4];" \
                 : "=r"((r)[0]), "=r"((r)[1]), "=r"((r)[2]), "=r"((r)[3])               \
                 : "r"(addr))

#define MMA_BF16(d, a, b0, b1)                                                     \
    asm volatile(                                                                  \
        "mma.sync.aligned.m16n8k16.row.col.f32.bf16.bf16.f32 "                     \
        "{%0,%1,%2,%3}, {%4,%5,%6,%7}, {%8,%9}, {%0,%1,%2,%3};"                    \
        : "+f"((d)[0]), "+f"((d)[1]), "+f"((d)[2]), "+f"((d)[3])                   \
        : "r"((a)[0]), "r"((a)[1]), "r"((a)[2]), "r"((a)[3]), "r"(b0), "r"(b1))

#define CP_ASYNC16(dst, src) \
    asm volatile("cp.async.cg.shared.global [%0], [%1], 16;" ::"r"(dst), "l"(src))
#define CP_ASYNC16Z(dst, src, sz) \
    asm volatile("cp.async.cg.shared.global [%0], [%1], 16, %2;" ::"r"(dst), "l"(src), "r"(sz))
#define CP_COMMIT asm volatile("cp.async.commit_group;" ::: "memory")
#define CP_WAIT(n) asm volatile("cp.async.wait_group %0;" ::"n"(n) : "memory")

__device__ __forceinline__ void split_pair(float u0, float u1, __nv_bfloat16* ph,
                                           __nv_bfloat16* pl) {
    __nv_bfloat16 h0 = __float2bfloat16_rn(u0);
    __nv_bfloat16 h1 = __float2bfloat16_rn(u1);
    __nv_bfloat16 l0 = __float2bfloat16_rn(u0 - __bfloat162float(h0));
    __nv_bfloat16 l1 = __float2bfloat16_rn(u1 - __bfloat162float(h1));
    uint32_t hp = ((uint32_t)__bfloat16_as_ushort(h1) << 16) | __bfloat16_as_ushort(h0);
    uint32_t lp = ((uint32_t)__bfloat16_as_ushort(l1) << 16) | __bfloat16_as_ushort(l0);
    *(uint32_t*)ph = hp;
    *(uint32_t*)pl = lp;
}
__device__ __forceinline__ void pack_hl(float a, float b, uint32_t& hi, uint32_t& lo) {
    __nv_bfloat16 ha = __float2bfloat16_rn(a);
    __nv_bfloat16 hb = __float2bfloat16_rn(b);
    __nv_bfloat16 la = __float2bfloat16_rn(a - __bfloat162float(ha));
    __nv_bfloat16 lb = __float2bfloat16_rn(b - __bfloat162float(hb));
    hi = ((uint32_t)__bfloat16_as_ushort(hb) << 16) | __bfloat16_as_ushort(ha);
    lo = ((uint32_t)__bfloat16_as_ushort(lb) << 16) | __bfloat16_as_ushort(la);
}

// ================= small kernels =================
__device__ __forceinline__ float block_sum_256(float v) {
    __shared__ float red[8];
    int lane = threadIdx.x & 31, wid = threadIdx.x >> 5;
#pragma unroll
    for (int o = 16; o > 0; o >>= 1) v += __shfl_down_sync(0xffffffffu, v, o);
    if (lane == 0) red[wid] = v;
    __syncthreads();
    if (wid == 0) {
        v = (lane < 8) ? red[lane] : 0.0f;
#pragma unroll
        for (int o = 4; o > 0; o >>= 1) v += __shfl_down_sync(0xffffffffu, v, o);
        if (lane == 0) red[0] = v;
    }
    __syncthreads();
    v = red[0];
    __syncthreads();
    return v;
}

__global__ void emb_kernel(const int* __restrict__ x, const float* __restrict__ we,
                           const float* __restrict__ pe, const float* __restrict__ tt,
                           float* __restrict__ out) {
    int s = blockIdx.x;
    int w = x[s];
    const float* wrow = we + (long long)w * D;
    const float* prow = pe + (long long)(s + 2) * D;
    for (int d = threadIdx.x; d < D; d += 256)
        out[s * D + d] = wrow[d] + prow[d] + tt[d];
}

__global__ void ln_kernel(const float* __restrict__ in, const float* __restrict__ g,
                          const float* __restrict__ b, float* __restrict__ out,
                          __nv_bfloat16* __restrict__ outh, __nv_bfloat16* __restrict__ outl) {
    int row = blockIdx.x;
    const float* x = in + row * D;
    float lsum = 0.0f;
    for (int d = threadIdx.x; d < D; d += 256) lsum += x[d];
    float mu = block_sum_256(lsum) * (1.0f / D);
    float lvar = 0.0f;
    for (int d = threadIdx.x; d < D; d += 256) {
        float t = x[d] - mu;
        lvar += t * t;
    }
    float var = block_sum_256(lvar) * (1.0f / D);
    float inv = rsqrtf(var + 1e-5f);
    for (int d = threadIdx.x; d < D; d += 256) {
        float y = (x[d] - mu) * inv * g[d] + b[d];
        out[row * D + d] = y;
        __nv_bfloat16 hv = __float2bfloat16_rn(y);
        outh[row * D + d] = hv;
        outl[row * D + d] = __float2bfloat16_rn(y - __bfloat162float(hv));
    }
}

// reduce 4 split-K partials + bias + residual, then LayerNorm; writes h + planes
__global__ void ln_red_kernel(const float* __restrict__ part, const float* __restrict__ bias,
                              const float* __restrict__ resid, const float* __restrict__ g,
                              const float* __restrict__ b, float* __restrict__ out,
                              __nv_bfloat16* __restrict__ outh,
                              __nv_bfloat16* __restrict__ outl) {
    int row = blockIdx.x;
    int tid = threadIdx.x;
    const long long rb = (long long)row * D;
    float v[3];
    float lsum = 0.0f;
#pragma unroll
    for (int i = 0; i < 3; i++) {
        int d = tid + i * 256;
        long long idx = rb + d;
        float s = part[idx] + part[(long long)S * D + idx] + part[2LL * S * D + idx] +
                  part[3LL * S * D + idx] + bias[d] + resid[idx];
        v[i] = s;
        lsum += s;
    }
    float mu = block_sum_256(lsum) * (1.0f / D);
    float lvar = 0.0f;
#pragma unroll
    for (int i = 0; i < 3; i++) {
        float t = v[i] - mu;
        lvar += t * t;
    }
    float var = block_sum_256(lvar) * (1.0f / D);
    float inv = rsqrtf(var + 1e-5f);
#pragma unroll
    for (int i = 0; i < 3; i++) {
        int d = tid + i * 256;
        float y = (v[i] - mu) * inv * g[d] + b[d];
        out[rb + d] = y;
        __nv_bfloat16 hv = __float2bfloat16_rn(y);
        outh[rb + d] = hv;
        outl[rb + d] = __float2bfloat16_rn(y - __bfloat162float(hv));
    }
}

// ---- batched transpose+split ----
__device__ __forceinline__ void tsp_body(const float* __restrict__ in,
                                         __nv_bfloat16* __restrict__ outh,
                                         __nv_bfloat16* __restrict__ outl, int R, int Ccols) {
    __shared__ float tile[32][33];
    int c0 = blockIdx.x * 32, r0 = blockIdx.y * 32;
    for (int i = threadIdx.y; i < 32; i += 8)
        tile[i][threadIdx.x] = in[(long long)(r0 + i) * Ccols + c0 + threadIdx.x];
    __syncthreads();
    for (int i = threadIdx.y; i < 32; i += 8) {
        float v = tile[threadIdx.x][i];
        __nv_bfloat16 hv = __float2bfloat16_rn(v);
        __nv_bfloat16 lv = __float2bfloat16_rn(v - __bfloat162float(hv));
        long long o = (long long)(c0 + i) * R + r0 + threadIdx.x;
        outh[o] = hv;
        outl[o] = lv;
    }
}
__global__ void tsp_dd(const float* __restrict__ Wq, const float* __restrict__ Wk,
                       const float* __restrict__ Wv, const float* __restrict__ Wo,
                       __nv_bfloat16* __restrict__ wTh, __nv_bfloat16* __restrict__ wTl) {
    int l = blockIdx.z >> 2, m = blockIdx.z & 3;
    const float* src = (m == 0 ? Wq : m == 1 ? Wk : m == 2 ? Wv : Wo) + (long long)l * D * D;
    long long dst = (long long)l * WT_PER_LAYER + (m < 3 ? OQKV + (long long)m * D * D : OO);
    tsp_body(src, wTh + dst, wTl + dst, D, D);
}
__global__ void tsp_wi(const float* __restrict__ Wi, __nv_bfloat16* __restrict__ wTh,
                       __nv_bfloat16* __restrict__ wTl) {
    int l = blockIdx.z;
    long long dst = (long long)l * WT_PER_LAYER + OI;
    tsp_body(Wi + (long long)l * D * FF, wTh + dst, wTl + dst, D, FF);
}
__global__ void tsp_wd(const float* __restrict__ Wd, __nv_bfloat16* __restrict__ wTh,
                       __nv_bfloat16* __restrict__ wTl) {
    int l = blockIdx.z;
    long long dst = (long long)l * WT_PER_LAYER + OD;
    tsp_body(Wd + (long long)l * FF * D, wTh + dst, wTl + dst, FF, D);
}

// ===== bf16x3 GEMM: 64x128 tile, BK=64, 2-stage single-sync, 2 CTAs/SM =====
#define BMT 64
#define BN 128
#define BK 64
#define GOFF_AL 8192
#define GOFF_BH 16384
#define GOFF_BL 32768
#define GSTG 49152
#define SMEM_G (2 * GSTG)

// EPI: 0 = bias -> qkv planes (Q scaled); 1 = bias+gelu -> planes;
//      2 = bias+resid -> fp32;      3 = raw split-K partial -> fp32 slice buffer
template <int EPI>
__global__ __launch_bounds__(256, 2) void mgemm(
    const __nv_bfloat16* __restrict__ Ah_g, const __nv_bfloat16* __restrict__ Al_g,
    const __nv_bfloat16* __restrict__ Bh_g, const __nv_bfloat16* __restrict__ Bl_g,
    const float* __restrict__ b0, const float* __restrict__ b1, const float* __restrict__ b2,
    const float* __restrict__ resid, float* __restrict__ C0,
    __nv_bfloat16* __restrict__ P0h, __nv_bfloat16* __restrict__ P0l,
    __nv_bfloat16* __restrict__ P1h, __nv_bfloat16* __restrict__ P1l,
    __nv_bfloat16* __restrict__ P2h, __nv_bfloat16* __restrict__ P2l,
    int Nst, int K, int Kst) {
    extern __shared__ char smem[];
    uint32_t sb = smem_u32(smem);
    int tid = threadIdx.x;
    int lane = tid & 31;
    int wid = tid >> 5;
    int wm = wid >> 2;
    int wn = wid & 3;
    int m0 = blockIdx.y * BMT;
    int n0 = blockIdx.x * BN;
    int z = (EPI == 3) ? blockIdx.z : 0;
    long long zoff = (long long)z * K * 2;  // byte offset of K-slice

    const char* Ahb = (const char*)Ah_g + ((long long)m0 * Kst) * 2 + zoff;
    const char* Alb = (const char*)Al_g + ((long long)m0 * Kst) * 2 + zoff;
    const char* Bhb = (const char*)Bh_g + ((long long)n0 * Kst) * 2 + zoff;
    const char* Blb = (const char*)Bl_g + ((long long)n0 * Kst) * 2 + zoff;
    const long long rowstride = (long long)Kst * 2;

    float acc[2][4][4];
#pragma unroll
    for (int i = 0; i < 2; i++)
#pragma unroll
        for (int j = 0; j < 4; j++)
#pragma unroll
            for (int r = 0; r < 4; r++) acc[i][j][r] = 0.0f;

    const int lrow = lane & 15;
    const int lhalf = lane >> 4;
    const int T = K / BK;

    int rowa[2], cba[2];
    uint32_t offa[2];
#pragma unroll
    for (int i = 0; i < 2; i++) {
        int ck = i * 256 + tid;
        rowa[i] = ck >> 3;
        cba[i] = (ck & 7) * 16;
        offa[i] = SWZ128((uint32_t)(rowa[i] * 128 + cba[i]));
    }
    int rowb[4], cbb[4];
    uint32_t offb[4];
#pragma unroll
    for (int i = 0; i < 4; i++) {
        int ck = i * 256 + tid;
        rowb[i] = ck >> 3;
        cbb[i] = (ck & 7) * 16;
        offb[i] = SWZ128((uint32_t)(rowb[i] * 128 + cbb[i]));
    }

#define LOAD_STAGE(t, s)                                                \
    do {                                                                \
        uint32_t stg = sb + (s) * GSTG;                                 \
        long long kb = (long long)(t) * (BK * 2);                       \
        _Pragma("unroll") for (int i = 0; i < 2; i++) {                 \
            long long src = rowa[i] * rowstride + kb + cba[i];          \
            CP_ASYNC16(stg + offa[i], Ahb + src);                       \
            CP_ASYNC16(stg + GOFF_AL + offa[i], Alb + src);             \
        }                                                               \
        _Pragma("unroll") for (int i = 0; i < 4; i++) {                 \
            long long src = rowb[i] * rowstride + kb + cbb[i];          \
            CP_ASYNC16(stg + GOFF_BH + offb[i], Bhb + src);             \
            CP_ASYNC16(stg + GOFF_BL + offb[i], Blb + src);             \
        }                                                               \
    } while (0)

    LOAD_STAGE(0, 0);
    CP_COMMIT;

    for (int t = 0; t < T; t++) {
        CP_WAIT(0);
        __syncthreads();
        if (t + 1 < T) {
            LOAD_STAGE(t + 1, (t + 1) & 1);
            CP_COMMIT;
        }
        uint32_t stg = sb + (t & 1) * GSTG;
#pragma unroll
        for (int ks = 0; ks < 4; ks++) {
            int kb = ks * 32 + lhalf * 16;
            uint32_t ah[2][4], al[2][4], bh[2][4], bl[2][4];
#pragma unroll
            for (int mt = 0; mt < 2; mt++) {
                int r = wm * 32 + mt * 16 + lrow;
                uint32_t off = SWZ128((uint32_t)(r * 128 + kb));
                LDSM_X4(ah[mt], stg + off);
                LDSM_X4(al[mt], stg + GOFF_AL + off);
            }
#pragma unroll
            for (int g2 = 0; g2 < 2; g2++) {
                int r = wn * 32 + g2 * 16 + lrow;
                uint32_t off = SWZ128((uint32_t)(r * 128 + kb));
                LDSM_X4(bh[g2], stg + GOFF_BH + off);
                LDSM_X4(bl[g2], stg + GOFF_BL + off);
            }
#pragma unroll
            for (int mt = 0; mt < 2; mt++)
#pragma unroll
                for (int j = 0; j < 4; j++) {
                    uint32_t b0h = bh[j >> 1][j & 1], b1h = bh[j >> 1][(j & 1) + 2];
                    uint32_t b0l = bl[j >> 1][j & 1], b1l = bl[j >> 1][(j & 1) + 2];
                    MMA_BF16(acc[mt][j], ah[mt], b0h, b1h);
                    MMA_BF16(acc[mt][j], ah[mt], b0l, b1l);
                    MMA_BF16(acc[mt][j], al[mt], b0h, b1h);
                }
        }
    }

    // ---- epilogue ----
    int g = lane >> 2;
    int tig = lane & 3;

    const float* bias = b0;
    __nv_bfloat16 *Poh = P0h, *Pol = P0l;
    float* Cp = C0;
    int ncol0 = n0;
    int mat = 0;
    if (EPI == 0) {
        mat = n0 / 768;
        ncol0 = n0 % 768;
        bias = (mat == 0) ? b0 : ((mat == 1) ? b1 : b2);
        Poh = (mat == 0) ? P0h : ((mat == 1) ? P1h : P2h);
        Pol = (mat == 0) ? P0l : ((mat == 1) ? P1l : P2l);
    }
    if (EPI == 3) Cp = C0 + (long long)z * S * 768;
    const int ost = (EPI == 0 || EPI == 3) ? 768 : Nst;

#pragma unroll
    for (int mt = 0; mt < 2; mt++) {
#pragma unroll
        for (int j = 0; j < 4; j++) {
            int colrel = ncol0 + wn * 32 + j * 8 + tig * 2;
            float bia0 = (EPI == 3) ? 0.0f : bias[colrel];
            float bia1 = (EPI == 3) ? 0.0f : bias[colrel + 1];
#pragma unroll
            for (int half = 0; half < 2; half++) {
                int row = m0 + wm * 32 + mt * 16 + g + half * 8;
                long long rb = (long long)row * ost + colrel;
                float u0 = acc[mt][j][half * 2 + 0] + bia0;
                float u1 = acc[mt][j][half * 2 + 1] + bia1;
                if (EPI == 0) {
                    if (mat == 0) {
                        u0 *= QSC;
                        u1 *= QSC;
                    }
                    split_pair(u0, u1, Poh + rb, Pol + rb);
                } else if (EPI == 1) {
                    u0 = 0.5f * u0 * (1.0f + erff(u0 * 0.70710678118654752f));
                    u1 = 0.5f * u1 * (1.0f + erff(u1 * 0.70710678118654752f));
                    split_pair(u0, u1, Poh + rb, Pol + rb);
                } else if (EPI == 2) {
                    u0 += resid[rb];
                    u1 += resid[rb + 1];
                    *(float2*)(&Cp[rb]) = make_float2(u0, u1);
                } else {
                    *(float2*)(&Cp[rb]) = make_float2(u0, u1);
                }
            }
        }
    }
}

// ================= tensor-core sliding-window attention =================
#define AQR 128
#define AKT 64
#define ANT 10
#define AST_BASE 32768
#define ATT_SMEM (32768 + 2 * 32768)

__global__ __launch_bounds__(256, 2) void attn_tc(
    const __nv_bfloat16* __restrict__ qh, const __nv_bfloat16* __restrict__ ql,
    const __nv_bfloat16* __restrict__ kh, const __nv_bfloat16* __restrict__ kl,
    const __nv_bfloat16* __restrict__ vh, const __nv_bfloat16* __restrict__ vl,
    __nv_bfloat16* __restrict__ aoh, __nv_bfloat16* __restrict__ aol) {
    extern __shared__ char smem[];
    uint32_t sb = smem_u32(smem);
    int tid = threadIdx.x;
    int lane = tid & 31;
    int wid = tid >> 5;
    int c = blockIdx.x;
    int h = blockIdx.y;
    const int q0g = c * AQR;
    const int cbase = q0g - W;
    const int lrow = lane & 15;
    const int lhalf = lane >> 4;
    const int wr0 = wid * 16;

#pragma unroll
    for (int i = 0; i < 4; i++) {
        int id = i * 256 + tid;
        int row = id >> 3;
        int cb = (id & 7) * 16;
        long long gsrc = ((long long)(q0g + row) * D + h * DH) * 2 + cb;
        uint32_t dst = sb + SWZ128((uint32_t)(row * 128 + cb));
        CP_ASYNC16(dst, (const char*)qh + gsrc);
        CP_ASYNC16(dst + 16384, (const char*)ql + gsrc);
    }

#define ATT_LOAD(kt, s)                                                               \
    do {                                                                              \
        uint32_t stb = sb + AST_BASE + (s) * 32768;                                   \
        _Pragma("unroll") for (int pl_ = 0; pl_ < 4; pl_++) {                         \
            const char* gp = (pl_ == 0)   ? (const char*)kh                           \
                             : (pl_ == 1) ? (const char*)kl                           \
                             : (pl_ == 2) ? (const char*)vh                           \
                                          : (const char*)vl;                          \
            _Pragma("unroll") for (int j_ = 0; j_ < 2; j_++) {                        \
                int rem = j_ * 256 + tid;                                             \
                int row = rem >> 3;                                                   \
                int cb = (rem & 7) * 16;                                              \
                int kg = cbase + (kt) * AKT + row;                                    \
                int ok = (kg >= 0 && kg < S);                                         \
                int kgc = ok ? kg : 0;                                                \
                long long gsrc = ((long long)kgc * D + h * DH) * 2 + cb;              \
                CP_ASYNC16Z(stb + pl_ * 8192 + SWZ128((uint32_t)(row * 128 + cb)),    \
                            gp + gsrc, ok ? 16 : 0);                                  \
            }                                                                         \
        }                                                                             \
    } while (0)

    ATT_LOAD(0, 0);
    CP_COMMIT;

    float acc[8][4];
#pragma unroll
    for (int nf = 0; nf < 8; nf++)
#pragma unroll
        for (int e = 0; e < 4; e++) acc[nf][e] = 0.0f;
    float mrow[2] = {-1e30f, -1e30f};
    float lrowv[2] = {0.0f, 0.0f};

    for (int kt = 0; kt < ANT; kt++) {
        CP_WAIT(0);
        __syncthreads();
        if (kt + 1 < ANT) {
            ATT_LOAD(kt + 1, (kt + 1) & 1);
            CP_COMMIT;
        }
        int jg0 = kt * AKT;
        bool active = (jg0 + AKT > wr0) && (jg0 <= wr0 + 15 + 2 * W);
        if (active) {
            uint32_t stb = sb + AST_BASE + (kt & 1) * 32768;
            uint32_t KH = stb, KL = stb + 8192, VH = stb + 16384, VL = stb + 24576;

            float sf[8][4];
#pragma unroll
            for (int nf = 0; nf < 8; nf++)
#pragma unroll
                for (int e = 0; e < 4; e++) sf[nf][e] = 0.0f;

#pragma unroll
            for (int ks = 0; ks < 4; ks++) {
                int kb = ks * 32 + lhalf * 16;
                uint32_t qhf[4], qlf[4];
                uint32_t qoff = SWZ128((uint32_t)((wr0 + lrow) * 128 + kb));
                LDSM_X4(qhf, sb + qoff);
                LDSM_X4(qlf, sb + 16384 + qoff);
#pragma unroll
                for (int nf2 = 0; nf2 < 4; nf2++) {
                    uint32_t khf[4], klf[4];
                    uint32_t off = SWZ128((uint32_t)((nf2 * 16 + lrow) * 128 + kb));
                    LDSM_X4(khf, KH + off);
                    LDSM_X4(klf, KL + off);
#pragma unroll
                    for (int hf = 0; hf < 2; hf++) {
                        int nf = nf2 * 2 + hf;
                        uint32_t b0h = khf[hf], b1h = khf[hf + 2];
                        uint32_t b0l = klf[hf], b1l = klf[hf + 2];
                        MMA_BF16(sf[nf], qhf, b0h, b1h);
                        MMA_BF16(sf[nf], qhf, b0l, b1l);
                        MMA_BF16(sf[nf], qlf, b0h, b1h);
                    }
                }
            }

            int rA = wr0 + (lane >> 2);
            int rB = rA + 8;
#pragma unroll
            for (int nf = 0; nf < 8; nf++)
#pragma unroll
                for (int e = 0; e < 4; e++) {
                    int col = jg0 + nf * 8 + (lane & 3) * 2 + (e & 1);
                    int row = (e < 2) ? rA : rB;
                    int kg = cbase + col;
                    bool ok = (col >= row) && (col <= row + 2 * W) && (kg >= 0) && (kg < S);
                    if (!ok) sf[nf][e] = -1e30f;
                }
            float mA = -1e30f, mB = -1e30f;
#pragma unroll
            for (int nf = 0; nf < 8; nf++) {
                mA = fmaxf(mA, fmaxf(sf[nf][0], sf[nf][1]));
                mB = fmaxf(mB, fmaxf(sf[nf][2], sf[nf][3]));
            }
            mA = fmaxf(mA, __shfl_xor_sync(0xffffffffu, mA, 1));
            mA = fmaxf(mA, __shfl_xor_sync(0xffffffffu, mA, 2));
            mB = fmaxf(mB, __shfl_xor_sync(0xffffffffu, mB, 1));
            mB = fmaxf(mB, __shfl_xor_sync(0xffffffffu, mB, 2));
            float mnA = fmaxf(mrow[0], mA);
            float mnB = fmaxf(mrow[1], mB);
            float scA = exp2f(mrow[0] - mnA);
            float scB = exp2f(mrow[1] - mnB);
            float sumA = 0.0f, sumB = 0.0f;
#pragma unroll
            for (int nf = 0; nf < 8; nf++) {
                float p0 = exp2f(sf[nf][0] - mnA);
                float p1 = exp2f(sf[nf][1] - mnA);
                float p2 = exp2f(sf[nf][2] - mnB);
                float p3 = exp2f(sf[nf][3] - mnB);
                sf[nf][0] = p0;
                sf[nf][1] = p1;
                sf[nf][2] = p2;
                sf[nf][3] = p3;
                sumA += p0 + p1;
                sumB += p2 + p3;
            }
            sumA += __shfl_xor_sync(0xffffffffu, sumA, 1);
            sumA += __shfl_xor_sync(0xffffffffu, sumA, 2);
            sumB += __shfl_xor_sync(0xffffffffu, sumB, 1);
            sumB += __shfl_xor_sync(0xffffffffu, sumB, 2);
            lrowv[0] = lrowv[0] * scA + sumA;
            lrowv[1] = lrowv[1] * scB + sumB;
#pragma unroll
            for (int of = 0; of < 8; of++) {
                acc[of][0] *= scA;
                acc[of][1] *= scA;
                acc[of][2] *= scB;
                acc[of][3] *= scB;
            }
            mrow[0] = mnA;
            mrow[1] = mnB;

#pragma unroll
            for (int ks2 = 0; ks2 < 4; ks2++) {
                const float* s0 = sf[2 * ks2];
                const float* s1 = sf[2 * ks2 + 1];
                uint32_t pah[4], pal[4];
                pack_hl(s0[0], s0[1], pah[0], pal[0]);
                pack_hl(s0[2], s0[3], pah[1], pal[1]);
                pack_hl(s1[0], s1[1], pah[2], pal[2]);
                pack_hl(s1[2], s1[3], pah[3], pal[3]);
#pragma unroll
                for (int vf2 = 0; vf2 < 4; vf2++) {
                    uint32_t vhf[4], vlf[4];
                    uint32_t off =
                        SWZ128((uint32_t)((ks2 * 16 + lrow) * 128 + vf2 * 32 + lhalf * 16));
                    LDSM_X4_T(vhf, VH + off);
                    LDSM_X4_T(vlf, VL + off);
#pragma unroll
                    for (int hf = 0; hf < 2; hf++) {
                        int nf = vf2 * 2 + hf;
                        uint32_t b0h = vhf[hf * 2], b1h = vhf[hf * 2 + 1];
                        uint32_t b0l = vlf[hf * 2], b1l = vlf[hf * 2 + 1];
                        MMA_BF16(acc[nf], pah, b0h, b1h);
                        MMA_BF16(acc[nf], pah, b0l, b1l);
                        MMA_BF16(acc[nf], pal, b0h, b1h);
                    }
                }
            }
        }
    }

    {
        float invA = 1.0f / lrowv[0];
        float invB = 1.0f / lrowv[1];
        int rA = wr0 + (lane >> 2);
        long long baseA = (long long)(q0g + rA) * D + h * DH;
        long long baseB = baseA + 8LL * D;
#pragma unroll
        for (int nf = 0; nf < 8; nf++) {
            int col = nf * 8 + (lane & 3) * 2;
            split_pair(acc[nf][0] * invA, acc[nf][1] * invA, aoh + baseA + col,
                       aol + baseA + col);
            split_pair(acc[nf][2] * invB, acc[nf][3] * invB, aoh + baseB + col,
                       aol + baseB + col);
        }
    }
}

__global__ void head_kernel(const float* __restrict__ hrow, const float* __restrict__ w,
                            const float* __restrict__ b, float* __restrict__ out) {
    int o = threadIdx.x;
    float acc = b[o];
    for (int d = 0; d < D; d++) acc += hrow[d] * w[d * OUT + o];
    out[o] = acc;
}

// ================= launch =================
extern "C" void kernel_launch(void* const* d_in, const int* in_sizes, int n_in,
                              void* d_out, int out_size) {
    (void)in_sizes; (void)n_in; (void)out_size;
    const int* x = (const int*)d_in[0];
    const float* word_emb = (const float*)d_in[1];
    const float* pos_emb = (const float*)d_in[2];
    const float* tt_emb = (const float*)d_in[3];
    const float* elg = (const float*)d_in[4];
    const float* elb = (const float*)d_in[5];
    const float* Wq = (const float*)d_in[6];
    const float* bq = (const float*)d_in[7];
    const float* Wk = (const float*)d_in[8];
    const float* bk = (const float*)d_in[9];
    const float* Wv = (const float*)d_in[10];
    const float* bv = (const float*)d_in[11];
    const float* Wo = (const float*)d_in[12];
    const float* bo = (const float*)d_in[13];
    const float* g1 = (const float*)d_in[14];
    const float* b1 = (const float*)d_in[15];
    const float* Wi = (const float*)d_in[16];
    const float* bi = (const float*)d_in[17];
    const float* Wd = (const float*)d_in[18];
    const float* bd = (const float*)d_in[19];
    const float* g2 = (const float*)d_in[20];
    const float* b2 = (const float*)d_in[21];
    const float* ow = (const float*)d_in[22];
    const float* ob = (const float*)d_in[23];
    float* out = (float*)d_out;

    float *h, *t, *part;
    __nv_bfloat16 *qh, *ql, *kh, *kl, *vh, *vl, *hh, *hl, *ah, *al, *fh, *fl, *wTh, *wTl;
    cudaGetSymbolAddress((void**)&h, g_h);
    cudaGetSymbolAddress((void**)&t, g_t);
    cudaGetSymbolAddress((void**)&part, g_part);
    cudaGetSymbolAddress((void**)&qh, g_qh);
    cudaGetSymbolAddress((void**)&ql, g_ql);
    cudaGetSymbolAddress((void**)&kh, g_kh);
    cudaGetSymbolAddress((void**)&kl, g_kl);
    cudaGetSymbolAddress((void**)&vh, g_vh);
    cudaGetSymbolAddress((void**)&vl, g_vl);
    cudaGetSymbolAddress((void**)&hh, g_hh);
    cudaGetSymbolAddress((void**)&hl, g_hl);
    cudaGetSymbolAddress((void**)&ah, g_ah);
    cudaGetSymbolAddress((void**)&al, g_al);
    cudaGetSymbolAddress((void**)&fh, g_fh);
    cudaGetSymbolAddress((void**)&fl, g_fl);
    cudaGetSymbolAddress((void**)&wTh, g_wTh);
    cudaGetSymbolAddress((void**)&wTl, g_wTl);

    cudaFuncSetAttribute(mgemm<0>, cudaFuncAttributeMaxDynamicSharedMemorySize, SMEM_G);
    cudaFuncSetAttribute(mgemm<1>, cudaFuncAttributeMaxDynamicSharedMemorySize, SMEM_G);
    cudaFuncSetAttribute(mgemm<2>, cudaFuncAttributeMaxDynamicSharedMemorySize, SMEM_G);
    cudaFuncSetAttribute(mgemm<3>, cudaFuncAttributeMaxDynamicSharedMemorySize, SMEM_G);
    cudaFuncSetAttribute(attn_tc, cudaFuncAttributeMaxDynamicSharedMemorySize, ATT_SMEM);

    dim3 tb(32, 8);
    tsp_dd<<<dim3(D / 32, D / 32, 4 * L), tb>>>(Wq, Wk, Wv, Wo, wTh, wTl);
    emb_kernel<<<S, 256>>>(x, word_emb, pos_emb, tt_emb, t);
    ln_kernel<<<S, 256>>>(t, elg, elb, h, hh, hl);

    dim3 gqkv(2304 / BN, S / BMT);       // 18 x 64
    dim3 gproj(768 / BN, S / BMT);       // 6 x 64
    dim3 gff1(FF / BN, S / BMT);         // 24 x 64
    dim3 gff2(768 / BN, S / BMT, 4);     // 6 x 64 x 4 (split-K)
    dim3 gattn(S / AQR, H);              // 32 x 12

    for (int l = 0; l < L; l++) {
        long long lb = (long long)l * WT_PER_LAYER;

        mgemm<0><<<gqkv, 256, SMEM_G>>>(hh, hl, wTh + lb + OQKV, wTl + lb + OQKV,
                                        bq + l * D, bk + l * D, bv + l * D, nullptr,
                                        nullptr, qh, ql, kh, kl, vh, vl, 768, D, D);

        if (l == 0) {
            tsp_wi<<<dim3(FF / 32, D / 32, L), tb>>>(Wi, wTh, wTl);
            tsp_wd<<<dim3(D / 32, FF / 32, L), tb>>>(Wd, wTh, wTl);
        }

        attn_tc<<<gattn, 256, ATT_SMEM>>>(qh, ql, kh, kl, vh, vl, ah, al);

        mgemm<2><<<gproj, 256, SMEM_G>>>(ah, al, wTh + lb + OO, wTl + lb + OO,
                                         bo + l * D, nullptr, nullptr, h, t,
                                         nullptr, nullptr, nullptr, nullptr, nullptr, nullptr,
                                         768, D, D);
        ln_kernel<<<S, 256>>>(t, g1 + l * D, b1 + l * D, h, hh, hl);

        mgemm<1><<<gff1, 256, SMEM_G>>>(hh, hl, wTh + lb + OI, wTl + lb + OI,
                                        bi + l * FF, nullptr, nullptr, nullptr, nullptr,
                                        fh, fl, nullptr, nullptr, nullptr, nullptr, FF, D, D);

        // FF2: split-K=4 into partials, reduction fused into LN
        mgemm<3><<<gff2, 256, SMEM_G>>>(fh, fl, wTh + lb + OD, wTl + lb + OD,
                                        nullptr, nullptr, nullptr, nullptr, part,
                                        nullptr, nullptr, nullptr, nullptr, nullptr, nullptr,
                                        768, 768, FF);
        ln_red_kernel<<<S, 256>>>(part, bd + l * D, h, g2 + l * D, b2 + l * D, h, hh, hl);
    }

    head_kernel<<<1, 256>>>(h, ow, ob, out);
}

// round 16
// speedup vs baseline: 1.2598x; 1.0053x over previous
#include <cuda_runtime.h>
#include <cuda_bf16.h>
#include <math.h>
#include <stdint.h>

#define S 4096
#define D 768
#define H 12
#define DH 64
#define L 12
#define FF 3072
#define W 256
#define OUT 256

// ---------------- scratch ----------------
__device__ float g_h[S * D];
__device__ float g_t[S * D];
__device__ float g_part[4 * S * D];  // split-K partials
__device__ __nv_bfloat16 g_qh[S * D], g_ql[S * D];
__device__ __nv_bfloat16 g_kh[S * D], g_kl[S * D];
__device__ __nv_bfloat16 g_vh[S * D], g_vl[S * D];
__device__ __nv_bfloat16 g_hh[S * D], g_hl[S * D];
__device__ __nv_bfloat16 g_ah[S * D], g_al[S * D];
__device__ __nv_bfloat16 g_fh[S * FF], g_fl[S * FF];
#define WT_PER_LAYER (4 * D * D + 2 * D * FF)
__device__ __nv_bfloat16 g_wTh[L * WT_PER_LAYER];
__device__ __nv_bfloat16 g_wTl[L * WT_PER_LAYER];

#define QSC 0.18033688011112042f

#define OQKV 0LL
#define OO (2304LL * 768)
#define OI (OO + 768LL * 768)
#define OD (OI + 3072LL * 768)

// ================= helpers =================
__device__ __forceinline__ uint32_t smem_u32(const void* p) {
    uint32_t a;
    asm("{ .reg .u64 t; cvta.to.shared.u64 t, %1; cvt.u32.u64 %0, t; }" : "=r"(a) : "l"(p));
    return a;
}
#define SWZ128(off) ((off) ^ (((off) >> 3) & 0x70))

#define LDSM_X4(r, addr)                                                          \
    asm volatile("ldmatrix.sync.aligned.m8n8.x4.shared.b16 {%0,%1,%2,%3}, [%4];" \
                 : "=r"((r)[0]), "=r"((r)[1]), "=r"((r)[2]), "=r"((r)[3])         \
                 : "r"(addr))
#define LDSM_X4_T(r, addr)                                                              \
    asm volatile("ldmatrix.sync.aligned.m8n8.x4.trans.shared.b16 {%0,%1,%2,%3}, [%4];" \
                 : "=r"((r)[0]), "=r"((r)[1]), "=r"((r)[2]), "=r"((r)[3])               \
                 : "r"(addr))

#define MMA_BF16(d, a, b0, b1)                                                     \
    asm volatile(                                                                  \
        "mma.sync.aligned.m16n8k16.row.col.f32.bf16.bf16.f32 "                     \
        "{%0,%1,%2,%3}, {%4,%5,%6,%7}, {%8,%9}, {%0,%1,%2,%3};"                    \
        : "+f"((d)[0]), "+f"((d)[1]), "+f"((d)[2]), "+f"((d)[3])                   \
        : "r"((a)[0]), "r"((a)[1]), "r"((a)[2]), "r"((a)[3]), "r"(b0), "r"(b1))

#define CP_ASYNC16(dst, src) \
    asm volatile("cp.async.cg.shared.global [%0], [%1], 16;" ::"r"(dst), "l"(src))
#define CP_ASYNC16Z(dst, src, sz) \
    asm volatile("cp.async.cg.shared.global [%0], [%1], 16, %2;" ::"r"(dst), "l"(src), "r"(sz))
#define CP_COMMIT asm volatile("cp.async.commit_group;" ::: "memory")
#define CP_WAIT(n) asm volatile("cp.async.wait_group %0;" ::"n"(n) : "memory")

__device__ __forceinline__ void split_pair(float u0, float u1, __nv_bfloat16* ph,
                                           __nv_bfloat16* pl) {
    __nv_bfloat16 h0 = __float2bfloat16_rn(u0);
    __nv_bfloat16 h1 = __float2bfloat16_rn(u1);
    __nv_bfloat16 l0 = __float2bfloat16_rn(u0 - __bfloat162float(h0));
    __nv_bfloat16 l1 = __float2bfloat16_rn(u1 - __bfloat162float(h1));
    uint32_t hp = ((uint32_t)__bfloat16_as_ushort(h1) << 16) | __bfloat16_as_ushort(h0);
    uint32_t lp = ((uint32_t)__bfloat16_as_ushort(l1) << 16) | __bfloat16_as_ushort(l0);
    *(uint32_t*)ph = hp;
    *(uint32_t*)pl = lp;
}
__device__ __forceinline__ void pack_hl(float a, float b, uint32_t& hi, uint32_t& lo) {
    __nv_bfloat16 ha = __float2bfloat16_rn(a);
    __nv_bfloat16 hb = __float2bfloat16_rn(b);
    __nv_bfloat16 la = __float2bfloat16_rn(a - __bfloat162float(ha));
    __nv_bfloat16 lb = __float2bfloat16_rn(b - __bfloat162float(hb));
    hi = ((uint32_t)__bfloat16_as_ushort(hb) << 16) | __bfloat16_as_ushort(ha);
    lo = ((uint32_t)__bfloat16_as_ushort(lb) << 16) | __bfloat16_as_ushort(la);
}

// ================= small kernels =================
__device__ __forceinline__ float block_sum_256(float v) {
    __shared__ float red[8];
    int lane = threadIdx.x & 31, wid = threadIdx.x >> 5;
#pragma unroll
    for (int o = 16; o > 0; o >>= 1) v += __shfl_down_sync(0xffffffffu, v, o);
    if (lane == 0) red[wid] = v;
    __syncthreads();
    if (wid == 0) {
        v = (lane < 8) ? red[lane] : 0.0f;
#pragma unroll
        for (int o = 4; o > 0; o >>= 1) v += __shfl_down_sync(0xffffffffu, v, o);
        if (lane == 0) red[0] = v;
    }
    __syncthreads();
    v = red[0];
    __syncthreads();
    return v;
}

__global__ void emb_kernel(const int* __restrict__ x, const float* __restrict__ we,
                           const float* __restrict__ pe, const float* __restrict__ tt,
                           float* __restrict__ out) {
    int s = blockIdx.x;
    int w = x[s];
    const float* wrow = we + (long long)w * D;
    const float* prow = pe + (long long)(s + 2) * D;
    for (int d = threadIdx.x; d < D; d += 256)
        out[s * D + d] = wrow[d] + prow[d] + tt[d];
}

// LN with register row cache (embedding path)
__global__ void ln_kernel(const float* __restrict__ in, const float* __restrict__ g,
                          const float* __restrict__ b, float* __restrict__ out,
                          __nv_bfloat16* __restrict__ outh, __nv_bfloat16* __restrict__ outl) {
    int row = blockIdx.x;
    int tid = threadIdx.x;
    const long long rb = (long long)row * D;
    float v[3];
    float lsum = 0.0f;
#pragma unroll
    for (int i = 0; i < 3; i++) {
        v[i] = in[rb + tid + i * 256];
        lsum += v[i];
    }
    float mu = block_sum_256(lsum) * (1.0f / D);
    float lvar = 0.0f;
#pragma unroll
    for (int i = 0; i < 3; i++) {
        float t = v[i] - mu;
        lvar += t * t;
    }
    float var = block_sum_256(lvar) * (1.0f / D);
    float inv = rsqrtf(var + 1e-5f);
#pragma unroll
    for (int i = 0; i < 3; i++) {
        int d = tid + i * 256;
        float y = (v[i] - mu) * inv * g[d] + b[d];
        out[rb + d] = y;
        __nv_bfloat16 hv = __float2bfloat16_rn(y);
        outh[rb + d] = hv;
        outl[rb + d] = __float2bfloat16_rn(y - __bfloat162float(hv));
    }
}

// reduce SL split-K partials + bias + residual, then LayerNorm; writes h + planes
template <int SL>
__global__ void ln_red_kernel(const float* __restrict__ part, const float* __restrict__ bias,
                              const float* __restrict__ resid, const float* __restrict__ g,
                              const float* __restrict__ b, float* __restrict__ out,
                              __nv_bfloat16* __restrict__ outh,
                              __nv_bfloat16* __restrict__ outl) {
    int row = blockIdx.x;
    int tid = threadIdx.x;
    const long long rb = (long long)row * D;
    float v[3];
    float lsum = 0.0f;
#pragma unroll
    for (int i = 0; i < 3; i++) {
        int d = tid + i * 256;
        long long idx = rb + d;
        float s = bias[d] + resid[idx];
#pragma unroll
        for (int sl = 0; sl < SL; sl++) s += part[(long long)sl * S * D + idx];
        v[i] = s;
        lsum += s;
    }
    float mu = block_sum_256(lsum) * (1.0f / D);
    float lvar = 0.0f;
#pragma unroll
    for (int i = 0; i < 3; i++) {
        float t = v[i] - mu;
        lvar += t * t;
    }
    float var = block_sum_256(lvar) * (1.0f / D);
    float inv = rsqrtf(var + 1e-5f);
#pragma unroll
    for (int i = 0; i < 3; i++) {
        int d = tid + i * 256;
        float y = (v[i] - mu) * inv * g[d] + b[d];
        out[rb + d] = y;
        __nv_bfloat16 hv = __float2bfloat16_rn(y);
        outh[rb + d] = hv;
        outl[rb + d] = __float2bfloat16_rn(y - __bfloat162float(hv));
    }
}

// ---- batched transpose+split ----
__device__ __forceinline__ void tsp_body(const float* __restrict__ in,
                                         __nv_bfloat16* __restrict__ outh,
                                         __nv_bfloat16* __restrict__ outl, int R, int Ccols) {
    __shared__ float tile[32][33];
    int c0 = blockIdx.x * 32, r0 = blockIdx.y * 32;
    for (int i = threadIdx.y; i < 32; i += 8)
        tile[i][threadIdx.x] = in[(long long)(r0 + i) * Ccols + c0 + threadIdx.x];
    __syncthreads();
    for (int i = threadIdx.y; i < 32; i += 8) {
        float v = tile[threadIdx.x][i];
        __nv_bfloat16 hv = __float2bfloat16_rn(v);
        __nv_bfloat16 lv = __float2bfloat16_rn(v - __bfloat162float(hv));
        long long o = (long long)(c0 + i) * R + r0 + threadIdx.x;
        outh[o] = hv;
        outl[o] = lv;
    }
}
__global__ void tsp_dd(const float* __restrict__ Wq, const float* __restrict__ Wk,
                       const float* __restrict__ Wv, const float* __restrict__ Wo,
                       __nv_bfloat16* __restrict__ wTh, __nv_bfloat16* __restrict__ wTl) {
    int l = blockIdx.z >> 2, m = blockIdx.z & 3;
    const float* src = (m == 0 ? Wq : m == 1 ? Wk : m == 2 ? Wv : Wo) + (long long)l * D * D;
    long long dst = (long long)l * WT_PER_LAYER + (m < 3 ? OQKV + (long long)m * D * D : OO);
    tsp_body(src, wTh + dst, wTl + dst, D, D);
}
__global__ void tsp_wi(const float* __restrict__ Wi, __nv_bfloat16* __restrict__ wTh,
                       __nv_bfloat16* __restrict__ wTl) {
    int l = blockIdx.z;
    long long dst = (long long)l * WT_PER_LAYER + OI;
    tsp_body(Wi + (long long)l * D * FF, wTh + dst, wTl + dst, D, FF);
}
__global__ void tsp_wd(const float* __restrict__ Wd, __nv_bfloat16* __restrict__ wTh,
                       __nv_bfloat16* __restrict__ wTl) {
    int l = blockIdx.z;
    long long dst = (long long)l * WT_PER_LAYER + OD;
    tsp_body(Wd + (long long)l * FF * D, wTh + dst, wTl + dst, FF, D);
}

// ===== bf16x3 GEMM: 64x128 tile, BK=64, 2-stage single-sync, 2 CTAs/SM =====
#define BMT 64
#define BN 128
#define BK 64
#define GOFF_AL 8192
#define GOFF_BH 16384
#define GOFF_BL 32768
#define GSTG 49152
#define SMEM_G (2 * GSTG)

// EPI: 0 = bias -> qkv planes (Q scaled); 1 = bias+gelu -> planes;
//      3 = raw split-K partial -> fp32 slice buffer
template <int EPI>
__global__ __launch_bounds__(256, 2) void mgemm(
    const __nv_bfloat16* __restrict__ Ah_g, const __nv_bfloat16* __restrict__ Al_g,
    const __nv_bfloat16* __restrict__ Bh_g, const __nv_bfloat16* __restrict__ Bl_g,
    const float* __restrict__ b0, const float* __restrict__ b1, const float* __restrict__ b2,
    float* __restrict__ C0,
    __nv_bfloat16* __restrict__ P0h, __nv_bfloat16* __restrict__ P0l,
    __nv_bfloat16* __restrict__ P1h, __nv_bfloat16* __restrict__ P1l,
    __nv_bfloat16* __restrict__ P2h, __nv_bfloat16* __restrict__ P2l,
    int Nst, int K, int Kst) {
    extern __shared__ char smem[];
    uint32_t sb = smem_u32(smem);
    int tid = threadIdx.x;
    int lane = tid & 31;
    int wid = tid >> 5;
    int wm = wid >> 2;
    int wn = wid & 3;
    int m0 = blockIdx.y * BMT;
    int n0 = blockIdx.x * BN;
    int z = (EPI == 3) ? blockIdx.z : 0;
    long long zoff = (long long)z * K * 2;

    const char* Ahb = (const char*)Ah_g + ((long long)m0 * Kst) * 2 + zoff;
    const char* Alb = (const char*)Al_g + ((long long)m0 * Kst) * 2 + zoff;
    const char* Bhb = (const char*)Bh_g + ((long long)n0 * Kst) * 2 + zoff;
    const char* Blb = (const char*)Bl_g + ((long long)n0 * Kst) * 2 + zoff;
    const long long rowstride = (long long)Kst * 2;

    float acc[2][4][4];
#pragma unroll
    for (int i = 0; i < 2; i++)
#pragma unroll
        for (int j = 0; j < 4; j++)
#pragma unroll
            for (int r = 0; r < 4; r++) acc[i][j][r] = 0.0f;

    const int lrow = lane & 15;
    const int lhalf = lane >> 4;
    const int T = K / BK;

    int rowa[2], cba[2];
    uint32_t offa[2];
#pragma unroll
    for (int i = 0; i < 2; i++) {
        int ck = i * 256 + tid;
        rowa[i] = ck >> 3;
        cba[i] = (ck & 7) * 16;
        offa[i] = SWZ128((uint32_t)(rowa[i] * 128 + cba[i]));
    }
    int rowb[4], cbb[4];
    uint32_t offb[4];
#pragma unroll
    for (int i = 0; i < 4; i++) {
        int ck = i * 256 + tid;
        rowb[i] = ck >> 3;
        cbb[i] = (ck & 7) * 16;
        offb[i] = SWZ128((uint32_t)(rowb[i] * 128 + cbb[i]));
    }

#define LOAD_STAGE(t, s)                                                \
    do {                                                                \
        uint32_t stg = sb + (s) * GSTG;                                 \
        long long kb = (long long)(t) * (BK * 2);                       \
        _Pragma("unroll") for (int i = 0; i < 2; i++) {                 \
            long long src = rowa[i] * rowstride + kb + cba[i];          \
            CP_ASYNC16(stg + offa[i], Ahb + src);                       \
            CP_ASYNC16(stg + GOFF_AL + offa[i], Alb + src);             \
        }                                                               \
        _Pragma("unroll") for (int i = 0; i < 4; i++) {                 \
            long long src = rowb[i] * rowstride + kb + cbb[i];          \
            CP_ASYNC16(stg + GOFF_BH + offb[i], Bhb + src);             \
            CP_ASYNC16(stg + GOFF_BL + offb[i], Blb + src);             \
        }                                                               \
    } while (0)

    LOAD_STAGE(0, 0);
    CP_COMMIT;

    for (int t = 0; t < T; t++) {
        CP_WAIT(0);
        __syncthreads();
        if (t + 1 < T) {
            LOAD_STAGE(t + 1, (t + 1) & 1);
            CP_COMMIT;
        }
        uint32_t stg = sb + (t & 1) * GSTG;
#pragma unroll
        for (int ks = 0; ks < 4; ks++) {
            int kb = ks * 32 + lhalf * 16;
            uint32_t ah[2][4], al[2][4], bh[2][4], bl[2][4];
#pragma unroll
            for (int mt = 0; mt < 2; mt++) {
                int r = wm * 32 + mt * 16 + lrow;
                uint32_t off = SWZ128((uint32_t)(r * 128 + kb));
                LDSM_X4(ah[mt], stg + off);
                LDSM_X4(al[mt], stg + GOFF_AL + off);
            }
#pragma unroll
            for (int g2 = 0; g2 < 2; g2++) {
                int r = wn * 32 + g2 * 16 + lrow;
                uint32_t off = SWZ128((uint32_t)(r * 128 + kb));
                LDSM_X4(bh[g2], stg + GOFF_BH + off);
                LDSM_X4(bl[g2], stg + GOFF_BL + off);
            }
#pragma unroll
            for (int mt = 0; mt < 2; mt++)
#pragma unroll
                for (int j = 0; j < 4; j++) {
                    uint32_t b0h = bh[j >> 1][j & 1], b1h = bh[j >> 1][(j & 1) + 2];
                    uint32_t b0l = bl[j >> 1][j & 1], b1l = bl[j >> 1][(j & 1) + 2];
                    MMA_BF16(acc[mt][j], ah[mt], b0h, b1h);
                    MMA_BF16(acc[mt][j], ah[mt], b0l, b1l);
                    MMA_BF16(acc[mt][j], al[mt], b0h, b1h);
                }
        }
    }

    // ---- epilogue ----
    int g = lane >> 2;
    int tig = lane & 3;

    const float* bias = b0;
    __nv_bfloat16 *Poh = P0h, *Pol = P0l;
    float* Cp = C0;
    int ncol0 = n0;
    int mat = 0;
    if (EPI == 0) {
        mat = n0 / 768;
        ncol0 = n0 % 768;
        bias = (mat == 0) ? b0 : ((mat == 1) ? b1 : b2);
        Poh = (mat == 0) ? P0h : ((mat == 1) ? P1h : P2h);
        Pol = (mat == 0) ? P0l : ((mat == 1) ? P1l : P2l);
    }
    if (EPI == 3) Cp = C0 + (long long)z * S * 768;
    const int ost = (EPI == 0 || EPI == 3) ? 768 : Nst;

#pragma unroll
    for (int mt = 0; mt < 2; mt++) {
#pragma unroll
        for (int j = 0; j < 4; j++) {
            int colrel = ncol0 + wn * 32 + j * 8 + tig * 2;
            float bia0 = (EPI == 3) ? 0.0f : bias[colrel];
            float bia1 = (EPI == 3) ? 0.0f : bias[colrel + 1];
#pragma unroll
            for (int half = 0; half < 2; half++) {
                int row = m0 + wm * 32 + mt * 16 + g + half * 8;
                long long rb = (long long)row * ost + colrel;
                float u0 = acc[mt][j][half * 2 + 0] + bia0;
                float u1 = acc[mt][j][half * 2 + 1] + bia1;
                if (EPI == 0) {
                    if (mat == 0) {
                        u0 *= QSC;
                        u1 *= QSC;
                    }
                    split_pair(u0, u1, Poh + rb, Pol + rb);
                } else if (EPI == 1) {
                    u0 = 0.5f * u0 * (1.0f + erff(u0 * 0.70710678118654752f));
                    u1 = 0.5f * u1 * (1.0f + erff(u1 * 0.70710678118654752f));
                    split_pair(u0, u1, Poh + rb, Pol + rb);
                } else {
                    *(float2*)(&Cp[rb]) = make_float2(u0, u1);
                }
            }
        }
    }
}

// ================= tensor-core sliding-window attention =================
#define AQR 128
#define AKT 64
#define ANT 10
#define AST_BASE 32768
#define ATT_SMEM (32768 + 2 * 32768)

__global__ __launch_bounds__(256, 2) void attn_tc(
    const __nv_bfloat16* __restrict__ qh, const __nv_bfloat16* __restrict__ ql,
    const __nv_bfloat16* __restrict__ kh, const __nv_bfloat16* __restrict__ kl,
    const __nv_bfloat16* __restrict__ vh, const __nv_bfloat16* __restrict__ vl,
    __nv_bfloat16* __restrict__ aoh, __nv_bfloat16* __restrict__ aol) {
    extern __shared__ char smem[];
    uint32_t sb = smem_u32(smem);
    int tid = threadIdx.x;
    int lane = tid & 31;
    int wid = tid >> 5;
    int c = blockIdx.x;
    int h = blockIdx.y;
    const int q0g = c * AQR;
    const int cbase = q0g - W;
    const int lrow = lane & 15;
    const int lhalf = lane >> 4;
    const int wr0 = wid * 16;

#pragma unroll
    for (int i = 0; i < 4; i++) {
        int id = i * 256 + tid;
        int row = id >> 3;
        int cb = (id & 7) * 16;
        long long gsrc = ((long long)(q0g + row) * D + h * DH) * 2 + cb;
        uint32_t dst = sb + SWZ128((uint32_t)(row * 128 + cb));
        CP_ASYNC16(dst, (const char*)qh + gsrc);
        CP_ASYNC16(dst + 16384, (const char*)ql + gsrc);
    }

#define ATT_LOAD(kt, s)                                                               \
    do {                                                                              \
        uint32_t stb = sb + AST_BASE + (s) * 32768;                                   \
        _Pragma("unroll") for (int pl_ = 0; pl_ < 4; pl_++) {                         \
            const char* gp = (pl_ == 0)   ? (const char*)kh                           \
                             : (pl_ == 1) ? (const char*)kl                           \
                             : (pl_ == 2) ? (const char*)vh                           \
                                          : (const char*)vl;                          \
            _Pragma("unroll") for (int j_ = 0; j_ < 2; j_++) {                        \
                int rem = j_ * 256 + tid;                                             \
                int row = rem >> 3;                                                   \
                int cb = (rem & 7) * 16;                                              \
                int kg = cbase + (kt) * AKT + row;                                    \
                int ok = (kg >= 0 && kg < S);                                         \
                int kgc = ok ? kg : 0;                                                \
                long long gsrc = ((long long)kgc * D + h * DH) * 2 + cb;              \
                CP_ASYNC16Z(stb + pl_ * 8192 + SWZ128((uint32_t)(row * 128 + cb)),    \
                            gp + gsrc, ok ? 16 : 0);                                  \
            }                                                                         \
        }                                                                             \
    } while (0)

    ATT_LOAD(0, 0);
    CP_COMMIT;

    float acc[8][4];
#pragma unroll
    for (int nf = 0; nf < 8; nf++)
#pragma unroll
        for (int e = 0; e < 4; e++) acc[nf][e] = 0.0f;
    float mrow[2] = {-1e30f, -1e30f};
    float lrowv[2] = {0.0f, 0.0f};

    for (int kt = 0; kt < ANT; kt++) {
        CP_WAIT(0);
        __syncthreads();
        if (kt + 1 < ANT) {
            ATT_LOAD(kt + 1, (kt + 1) & 1);
            CP_COMMIT;
        }
        int jg0 = kt * AKT;
        bool active = (jg0 + AKT > wr0) && (jg0 <= wr0 + 15 + 2 * W);
        if (active) {
            uint32_t stb = sb + AST_BASE + (kt & 1) * 32768;
            uint32_t KH = stb, KL = stb + 8192, VH = stb + 16384, VL = stb + 24576;

            float sf[8][4];
#pragma unroll
            for (int nf = 0; nf < 8; nf++)
#pragma unroll
                for (int e = 0; e < 4; e++) sf[nf][e] = 0.0f;

#pragma unroll
            for (int ks = 0; ks < 4; ks++) {
                int kb = ks * 32 + lhalf * 16;
                uint32_t qhf[4], qlf[4];
                uint32_t qoff = SWZ128((uint32_t)((wr0 + lrow) * 128 + kb));
                LDSM_X4(qhf, sb + qoff);
                LDSM_X4(qlf, sb + 16384 + qoff);
#pragma unroll
                for (int nf2 = 0; nf2 < 4; nf2++) {
                    uint32_t khf[4], klf[4];
                    uint32_t off = SWZ128((uint32_t)((nf2 * 16 + lrow) * 128 + kb));
                    LDSM_X4(khf, KH + off);
                    LDSM_X4(klf, KL + off);
#pragma unroll
                    for (int hf = 0; hf < 2; hf++) {
                        int nf = nf2 * 2 + hf;
                        uint32_t b0h = khf[hf], b1h = khf[hf + 2];
                        uint32_t b0l = klf[hf], b1l = klf[hf + 2];
                        MMA_BF16(sf[nf], qhf, b0h, b1h);
                        MMA_BF16(sf[nf], qhf, b0l, b1l);
                        MMA_BF16(sf[nf], qlf, b0h, b1h);
                    }
                }
            }

            int rA = wr0 + (lane >> 2);
            int rB = rA + 8;
#pragma unroll
            for (int nf = 0; nf < 8; nf++)
#pragma unroll
                for (int e = 0; e < 4; e++) {
                    int col = jg0 + nf * 8 + (lane & 3) * 2 + (e & 1);
                    int row = (e < 2) ? rA : rB;
                    int kg = cbase + col;
                    bool ok = (col >= row) && (col <= row + 2 * W) && (kg >= 0) && (kg < S);
                    if (!ok) sf[nf][e] = -1e30f;
                }
            float mA = -1e30f, mB = -1e30f;
#pragma unroll
            for (int nf = 0; nf < 8; nf++) {
                mA = fmaxf(mA, fmaxf(sf[nf][0], sf[nf][1]));
                mB = fmaxf(mB, fmaxf(sf[nf][2], sf[nf][3]));
            }
            mA = fmaxf(mA, __shfl_xor_sync(0xffffffffu, mA, 1));
            mA = fmaxf(mA, __shfl_xor_sync(0xffffffffu, mA, 2));
            mB = fmaxf(mB, __shfl_xor_sync(0xffffffffu, mB, 1));
            mB = fmaxf(mB, __shfl_xor_sync(0xffffffffu, mB, 2));
            float mnA = fmaxf(mrow[0], mA);
            float mnB = fmaxf(mrow[1], mB);
            float scA = exp2f(mrow[0] - mnA);
            float scB = exp2f(mrow[1] - mnB);
            float sumA = 0.0f, sumB = 0.0f;
#pragma unroll
            for (int nf = 0; nf < 8; nf++) {
                float p0 = exp2f(sf[nf][0] - mnA);
                float p1 = exp2f(sf[nf][1] - mnA);
                float p2 = exp2f(sf[nf][2] - mnB);
                float p3 = exp2f(sf[nf][3] - mnB);
                sf[nf][0] = p0;
                sf[nf][1] = p1;
                sf[nf][2] = p2;
                sf[nf][3] = p3;
                sumA += p0 + p1;
                sumB += p2 + p3;
            }
            sumA += __shfl_xor_sync(0xffffffffu, sumA, 1);
            sumA += __shfl_xor_sync(0xffffffffu, sumA, 2);
            sumB += __shfl_xor_sync(0xffffffffu, sumB, 1);
            sumB += __shfl_xor_sync(0xffffffffu, sumB, 2);
            lrowv[0] = lrowv[0] * scA + sumA;
            lrowv[1] = lrowv[1] * scB + sumB;
#pragma unroll
            for (int of = 0; of < 8; of++) {
                acc[of][0] *= scA;
                acc[of][1] *= scA;
                acc[of][2] *= scB;
                acc[of][3] *= scB;
            }
            mrow[0] = mnA;
            mrow[1] = mnB;

#pragma unroll
            for (int ks2 = 0; ks2 < 4; ks2++) {
                const float* s0 = sf[2 * ks2];
                const float* s1 = sf[2 * ks2 + 1];
                uint32_t pah[4], pal[4];
                pack_hl(s0[0], s0[1], pah[0], pal[0]);
                pack_hl(s0[2], s0[3], pah[1], pal[1]);
                pack_hl(s1[0], s1[1], pah[2], pal[2]);
                pack_hl(s1[2], s1[3], pah[3], pal[3]);
#pragma unroll
                for (int vf2 = 0; vf2 < 4; vf2++) {
                    uint32_t vhf[4], vlf[4];
                    uint32_t off =
                        SWZ128((uint32_t)((ks2 * 16 + lrow) * 128 + vf2 * 32 + lhalf * 16));
                    LDSM_X4_T(vhf, VH + off);
                    LDSM_X4_T(vlf, VL + off);
#pragma unroll
                    for (int hf = 0; hf < 2; hf++) {
                        int nf = vf2 * 2 + hf;
                        uint32_t b0h = vhf[hf * 2], b1h = vhf[hf * 2 + 1];
                        uint32_t b0l = vlf[hf * 2], b1l = vlf[hf * 2 + 1];
                        MMA_BF16(acc[nf], pah, b0h, b1h);
                        MMA_BF16(acc[nf], pah, b0l, b1l);
                        MMA_BF16(acc[nf], pal, b0h, b1h);
                    }
                }
            }
        }
    }

    {
        float invA = 1.0f / lrowv[0];
        float invB = 1.0f / lrowv[1];
        int rA = wr0 + (lane >> 2);
        long long baseA = (long long)(q0g + rA) * D + h * DH;
        long long baseB = baseA + 8LL * D;
#pragma unroll
        for (int nf = 0; nf < 8; nf++) {
            int col = nf * 8 + (lane & 3) * 2;
            split_pair(acc[nf][0] * invA, acc[nf][1] * invA, aoh + baseA + col,
                       aol + baseA + col);
            split_pair(acc[nf][2] * invB, acc[nf][3] * invB, aoh + baseB + col,
                       aol + baseB + col);
        }
    }
}

__global__ void head_kernel(const float* __restrict__ hrow, const float* __restrict__ w,
                            const float* __restrict__ b, float* __restrict__ out) {
    int o = threadIdx.x;
    float acc = b[o];
    for (int d = 0; d < D; d++) acc += hrow[d] * w[d * OUT + o];
    out[o] = acc;
}

// ================= launch =================
extern "C" void kernel_launch(void* const* d_in, const int* in_sizes, int n_in,
                              void* d_out, int out_size) {
    (void)in_sizes; (void)n_in; (void)out_size;
    const int* x = (const int*)d_in[0];
    const float* word_emb = (const float*)d_in[1];
    const float* pos_emb = (const float*)d_in[2];
    const float* tt_emb = (const float*)d_in[3];
    const float* elg = (const float*)d_in[4];
    const float* elb = (const float*)d_in[5];
    const float* Wq = (const float*)d_in[6];
    const float* bq = (const float*)d_in[7];
    const float* Wk = (const float*)d_in[8];
    const float* bk = (const float*)d_in[9];
    const float* Wv = (const float*)d_in[10];
    const float* bv = (const float*)d_in[11];
    const float* Wo = (const float*)d_in[12];
    const float* bo = (const float*)d_in[13];
    const float* g1 = (const float*)d_in[14];
    const float* b1 = (const float*)d_in[15];
    const float* Wi = (const float*)d_in[16];
    const float* bi = (const float*)d_in[17];
    const float* Wd = (const float*)d_in[18];
    const float* bd = (const float*)d_in[19];
    const float* g2 = (const float*)d_in[20];
    const float* b2 = (const float*)d_in[21];
    const float* ow = (const float*)d_in[22];
    const float* ob = (const float*)d_in[23];
    float* out = (float*)d_out;

    float *h, *t, *part;
    __nv_bfloat16 *qh, *ql, *kh, *kl, *vh, *vl, *hh, *hl, *ah, *al, *fh, *fl, *wTh, *wTl;
    cudaGetSymbolAddress((void**)&h, g_h);
    cudaGetSymbolAddress((void**)&t, g_t);
    cudaGetSymbolAddress((void**)&part, g_part);
    cudaGetSymbolAddress((void**)&qh, g_qh);
    cudaGetSymbolAddress((void**)&ql, g_ql);
    cudaGetSymbolAddress((void**)&kh, g_kh);
    cudaGetSymbolAddress((void**)&kl, g_kl);
    cudaGetSymbolAddress((void**)&vh, g_vh);
    cudaGetSymbolAddress((void**)&vl, g_vl);
    cudaGetSymbolAddress((void**)&hh, g_hh);
    cudaGetSymbolAddress((void**)&hl, g_hl);
    cudaGetSymbolAddress((void**)&ah, g_ah);
    cudaGetSymbolAddress((void**)&al, g_al);
    cudaGetSymbolAddress((void**)&fh, g_fh);
    cudaGetSymbolAddress((void**)&fl, g_fl);
    cudaGetSymbolAddress((void**)&wTh, g_wTh);
    cudaGetSymbolAddress((void**)&wTl, g_wTl);

    cudaFuncSetAttribute(mgemm<0>, cudaFuncAttributeMaxDynamicSharedMemorySize, SMEM_G);
    cudaFuncSetAttribute(mgemm<1>, cudaFuncAttributeMaxDynamicSharedMemorySize, SMEM_G);
    cudaFuncSetAttribute(mgemm<3>, cudaFuncAttributeMaxDynamicSharedMemorySize, SMEM_G);
    cudaFuncSetAttribute(attn_tc, cudaFuncAttributeMaxDynamicSharedMemorySize, ATT_SMEM);

    dim3 tb(32, 8);
    tsp_dd<<<dim3(D / 32, D / 32, 4 * L), tb>>>(Wq, Wk, Wv, Wo, wTh, wTl);
    emb_kernel<<<S, 256>>>(x, word_emb, pos_emb, tt_emb, t);
    ln_kernel<<<S, 256>>>(t, elg, elb, h, hh, hl);

    dim3 gqkv(2304 / BN, S / BMT);     // 18 x 64
    dim3 gwo(768 / BN, S / BMT, 2);    // 6 x 64 x 2 (split-K=2)
    dim3 gff1(FF / BN, S / BMT);       // 24 x 64
    dim3 gff2(768 / BN, S / BMT, 4);   // 6 x 64 x 4 (split-K=4)
    dim3 gattn(S / AQR, H);            // 32 x 12

    for (int l = 0; l < L; l++) {
        long long lb = (long long)l * WT_PER_LAYER;

        mgemm<0><<<gqkv, 256, SMEM_G>>>(hh, hl, wTh + lb + OQKV, wTl + lb + OQKV,
                                        bq + l * D, bk + l * D, bv + l * D,
                                        nullptr, qh, ql, kh, kl, vh, vl, 768, D, D);

        if (l == 0) {
            tsp_wi<<<dim3(FF / 32, D / 32, L), tb>>>(Wi, wTh, wTl);
            tsp_wd<<<dim3(D / 32, FF / 32, L), tb>>>(Wd, wTh, wTl);
        }

        attn_tc<<<gattn, 256, ATT_SMEM>>>(qh, ql, kh, kl, vh, vl, ah, al);

        // Wo: split-K=2 partials, reduce fused into LN1
        mgemm<3><<<gwo, 256, SMEM_G>>>(ah, al, wTh + lb + OO, wTl + lb + OO,
                                       nullptr, nullptr, nullptr, part,
                                       nullptr, nullptr, nullptr, nullptr, nullptr, nullptr,
                                       768, 384, D);
        ln_red_kernel<2><<<S, 256>>>(part, bo + l * D, h, g1 + l * D, b1 + l * D, h, hh, hl);

        mgemm<1><<<gff1, 256, SMEM_G>>>(hh, hl, wTh + lb + OI, wTl + lb + OI,
                                        bi + l * FF, nullptr, nullptr, nullptr,
                                        fh, fl, nullptr, nullptr, nullptr, nullptr, FF, D, D);

        // FF2: split-K=4 partials, reduce fused into LN2
        mgemm<3><<<gff2, 256, SMEM_G>>>(fh, fl, wTh + lb + OD, wTl + lb + OD,
                                        nullptr, nullptr, nullptr, part,
                                        nullptr, nullptr, nullptr, nullptr, nullptr, nullptr,
                                        768, 768, FF);
        ln_red_kernel<4><<<S, 256>>>(part, bd + l * D, h, g2 + l * D, b2 + l * D, h, hh, hl);
    }

    head_kernel<<<1, 256>>>(h, ow, ob, out);
}

// round 17
// speedup vs baseline: 1.3049x; 1.0358x over previous
#include <cuda_runtime.h>
#include <cuda_bf16.h>
#include <math.h>
#include <stdint.h>

#define S 4096
#define D 768
#define H 12
#define DH 64
#define L 12
#define FF 3072
#define W 256
#define OUT 256

// ---------------- scratch ----------------
__device__ float g_h[S * D];
__device__ float g_part[4 * S * D];  // split-K partials
__device__ __nv_bfloat16 g_qh[S * D], g_ql[S * D];
__device__ __nv_bfloat16 g_kh[S * D];
__device__ __nv_bfloat16 g_vh[S * D];
__device__ __nv_bfloat16 g_hh[S * D], g_hl[S * D];
__device__ __nv_bfloat16 g_ah[S * D], g_al[S * D];
__device__ __nv_bfloat16 g_fh[S * FF], g_fl[S * FF];
#define WT_PER_LAYER (4 * D * D + 2 * D * FF)
__device__ __nv_bfloat16 g_wTh[L * WT_PER_LAYER];
__device__ __nv_bfloat16 g_wTl[L * WT_PER_LAYER];

#define QSC 0.18033688011112042f

#define OQKV 0LL
#define OO (2304LL * 768)
#define OI (OO + 768LL * 768)
#define OD (OI + 3072LL * 768)

// ================= helpers =================
__device__ __forceinline__ uint32_t smem_u32(const void* p) {
    uint32_t a;
    asm("{ .reg .u64 t; cvta.to.shared.u64 t, %1; cvt.u32.u64 %0, t; }" : "=r"(a) : "l"(p));
    return a;
}
#define SWZ128(off) ((off) ^ (((off) >> 3) & 0x70))

#define LDSM_X4(r, addr)                                                          \
    asm volatile("ldmatrix.sync.aligned.m8n8.x4.shared.b16 {%0,%1,%2,%3}, [%4];" \
                 : "=r"((r)[0]), "=r"((r)[1]), "=r"((r)[2]), "=r"((r)[3])         \
                 : "r"(addr))
#define LDSM_X4_T(r, addr)                                                              \
    asm volatile("ldmatrix.sync.aligned.m8n8.x4.trans.shared.b16 {%0,%1,%2,%3}, [%4];" \
                 : "=r"((r)[0]), "=r"((r)[1]), "=r"((r)[2]), "=r"((r)[3])               \
                 : "r"(addr))

#define MMA_BF16(d, a, b0, b1)                                                     \
    asm volatile(                                                                  \
        "mma.sync.aligned.m16n8k16.row.col.f32.bf16.bf16.f32 "                     \
        "{%0,%1,%2,%3}, {%4,%5,%6,%7}, {%8,%9}, {%0,%1,%2,%3};"                    \
        : "+f"((d)[0]), "+f"((d)[1]), "+f"((d)[2]), "+f"((d)[3])                   \
        : "r"((a)[0]), "r"((a)[1]), "r"((a)[2]), "r"((a)[3]), "r"(b0), "r"(b1))

#define CP_ASYNC16(dst, src) \
    asm volatile("cp.async.cg.shared.global [%0], [%1], 16;" ::"r"(dst), "l"(src))
#define CP_ASYNC16Z(dst, src, sz) \
    asm volatile("cp.async.cg.shared.global [%0], [%1], 16, %2;" ::"r"(dst), "l"(src), "r"(sz))
#define CP_COMMIT asm volatile("cp.async.commit_group;" ::: "memory")
#define CP_WAIT(n) asm volatile("cp.async.wait_group %0;" ::"n"(n) : "memory")

__device__ __forceinline__ void split_pair(float u0, float u1, __nv_bfloat16* ph,
                                           __nv_bfloat16* pl) {
    __nv_bfloat16 h0 = __float2bfloat16_rn(u0);
    __nv_bfloat16 h1 = __float2bfloat16_rn(u1);
    __nv_bfloat16 l0 = __float2bfloat16_rn(u0 - __bfloat162float(h0));
    __nv_bfloat16 l1 = __float2bfloat16_rn(u1 - __bfloat162float(h1));
    uint32_t hp = ((uint32_t)__bfloat16_as_ushort(h1) << 16) | __bfloat16_as_ushort(h0);
    uint32_t lp = ((uint32_t)__bfloat16_as_ushort(l1) << 16) | __bfloat16_as_ushort(l0);
    *(uint32_t*)ph = hp;
    *(uint32_t*)pl = lp;
}
__device__ __forceinline__ void pack_hi(float u0, float u1, __nv_bfloat16* ph) {
    __nv_bfloat16 h0 = __float2bfloat16_rn(u0);
    __nv_bfloat16 h1 = __float2bfloat16_rn(u1);
    uint32_t hp = ((uint32_t)__bfloat16_as_ushort(h1) << 16) | __bfloat16_as_ushort(h0);
    *(uint32_t*)ph = hp;
}
__device__ __forceinline__ void pack_hl(float a, float b, uint32_t& hi, uint32_t& lo) {
    __nv_bfloat16 ha = __float2bfloat16_rn(a);
    __nv_bfloat16 hb = __float2bfloat16_rn(b);
    __nv_bfloat16 la = __float2bfloat16_rn(a - __bfloat162float(ha));
    __nv_bfloat16 lb = __float2bfloat16_rn(b - __bfloat162float(hb));
    hi = ((uint32_t)__bfloat16_as_ushort(hb) << 16) | __bfloat16_as_ushort(ha);
    lo = ((uint32_t)__bfloat16_as_ushort(lb) << 16) | __bfloat16_as_ushort(la);
}

// ================= small kernels =================
__device__ __forceinline__ float block_sum_256(float v) {
    __shared__ float red[8];
    int lane = threadIdx.x & 31, wid = threadIdx.x >> 5;
#pragma unroll
    for (int o = 16; o > 0; o >>= 1) v += __shfl_down_sync(0xffffffffu, v, o);
    if (lane == 0) red[wid] = v;
    __syncthreads();
    if (wid == 0) {
        v = (lane < 8) ? red[lane] : 0.0f;
#pragma unroll
        for (int o = 4; o > 0; o >>= 1) v += __shfl_down_sync(0xffffffffu, v, o);
        if (lane == 0) red[0] = v;
    }
    __syncthreads();
    v = red[0];
    __syncthreads();
    return v;
}

__global__ void emb_kernel(const int* __restrict__ x, const float* __restrict__ we,
                           const float* __restrict__ pe, const float* __restrict__ tt,
                           float* __restrict__ out) {
    int s = blockIdx.x;
    int w = x[s];
    const float* wrow = we + (long long)w * D;
    const float* prow = pe + (long long)(s + 2) * D;
    for (int d = threadIdx.x; d < D; d += 256)
        out[s * D + d] = wrow[d] + prow[d] + tt[d];
}

__global__ void ln_kernel(const float* __restrict__ in, const float* __restrict__ g,
                          const float* __restrict__ b, float* __restrict__ out,
                          __nv_bfloat16* __restrict__ outh, __nv_bfloat16* __restrict__ outl) {
    int row = blockIdx.x;
    int tid = threadIdx.x;
    const long long rb = (long long)row * D;
    float v[3];
    float lsum = 0.0f;
#pragma unroll
    for (int i = 0; i < 3; i++) {
        v[i] = in[rb + tid + i * 256];
        lsum += v[i];
    }
    float mu = block_sum_256(lsum) * (1.0f / D);
    float lvar = 0.0f;
#pragma unroll
    for (int i = 0; i < 3; i++) {
        float t = v[i] - mu;
        lvar += t * t;
    }
    float var = block_sum_256(lvar) * (1.0f / D);
    float inv = rsqrtf(var + 1e-5f);
#pragma unroll
    for (int i = 0; i < 3; i++) {
        int d = tid + i * 256;
        float y = (v[i] - mu) * inv * g[d] + b[d];
        out[rb + d] = y;
        __nv_bfloat16 hv = __float2bfloat16_rn(y);
        outh[rb + d] = hv;
        outl[rb + d] = __float2bfloat16_rn(y - __bfloat162float(hv));
    }
}

// reduce SL split-K partials + bias + residual, then LayerNorm; writes h + planes
template <int SL>
__global__ void ln_red_kernel(const float* __restrict__ part, const float* __restrict__ bias,
                              const float* __restrict__ resid, const float* __restrict__ g,
                              const float* __restrict__ b, float* __restrict__ out,
                              __nv_bfloat16* __restrict__ outh,
                              __nv_bfloat16* __restrict__ outl) {
    int row = blockIdx.x;
    int tid = threadIdx.x;
    const long long rb = (long long)row * D;
    float v[3];
    float lsum = 0.0f;
#pragma unroll
    for (int i = 0; i < 3; i++) {
        int d = tid + i * 256;
        long long idx = rb + d;
        float s = bias[d] + resid[idx];
#pragma unroll
        for (int sl = 0; sl < SL; sl++) s += part[(long long)sl * S * D + idx];
        v[i] = s;
        lsum += s;
    }
    float mu = block_sum_256(lsum) * (1.0f / D);
    float lvar = 0.0f;
#pragma unroll
    for (int i = 0; i < 3; i++) {
        float t = v[i] - mu;
        lvar += t * t;
    }
    float var = block_sum_256(lvar) * (1.0f / D);
    float inv = rsqrtf(var + 1e-5f);
#pragma unroll
    for (int i = 0; i < 3; i++) {
        int d = tid + i * 256;
        float y = (v[i] - mu) * inv * g[d] + b[d];
        out[rb + d] = y;
        __nv_bfloat16 hv = __float2bfloat16_rn(y);
        outh[rb + d] = hv;
        outl[rb + d] = __float2bfloat16_rn(y - __bfloat162float(hv));
    }
}

// ---- batched transpose+split ----
__device__ __forceinline__ void tsp_body(const float* __restrict__ in,
                                         __nv_bfloat16* __restrict__ outh,
                                         __nv_bfloat16* __restrict__ outl, int R, int Ccols) {
    __shared__ float tile[32][33];
    int c0 = blockIdx.x * 32, r0 = blockIdx.y * 32;
    for (int i = threadIdx.y; i < 32; i += 8)
        tile[i][threadIdx.x] = in[(long long)(r0 + i) * Ccols + c0 + threadIdx.x];
    __syncthreads();
    for (int i = threadIdx.y; i < 32; i += 8) {
        float v = tile[threadIdx.x][i];
        __nv_bfloat16 hv = __float2bfloat16_rn(v);
        __nv_bfloat16 lv = __float2bfloat16_rn(v - __bfloat162float(hv));
        long long o = (long long)(c0 + i) * R + r0 + threadIdx.x;
        outh[o] = hv;
        outl[o] = lv;
    }
}
__global__ void tsp_dd(const float* __restrict__ Wq, const float* __restrict__ Wk,
                       const float* __restrict__ Wv, const float* __restrict__ Wo,
                       __nv_bfloat16* __restrict__ wTh, __nv_bfloat16* __restrict__ wTl) {
    int l = blockIdx.z >> 2, m = blockIdx.z & 3;
    const float* src = (m == 0 ? Wq : m == 1 ? Wk : m == 2 ? Wv : Wo) + (long long)l * D * D;
    long long dst = (long long)l * WT_PER_LAYER + (m < 3 ? OQKV + (long long)m * D * D : OO);
    tsp_body(src, wTh + dst, wTl + dst, D, D);
}
__global__ void tsp_wi(const float* __restrict__ Wi, __nv_bfloat16* __restrict__ wTh,
                       __nv_bfloat16* __restrict__ wTl) {
    int l = blockIdx.z;
    long long dst = (long long)l * WT_PER_LAYER + OI;
    tsp_body(Wi + (long long)l * D * FF, wTh + dst, wTl + dst, D, FF);
}
__global__ void tsp_wd(const float* __restrict__ Wd, __nv_bfloat16* __restrict__ wTh,
                       __nv_bfloat16* __restrict__ wTl) {
    int l = blockIdx.z;
    long long dst = (long long)l * WT_PER_LAYER + OD;
    tsp_body(Wd + (long long)l * FF * D, wTh + dst, wTl + dst, FF, D);
}

// ===== bf16x3 GEMM: 64x128 tile, BK=64, 2-stage single-sync, 2 CTAs/SM =====
#define BMT 64
#define BN 128
#define BK 64
#define GOFF_AL 8192
#define GOFF_BH 16384
#define GOFF_BL 32768
#define GSTG 49152
#define SMEM_G (2 * GSTG)

// EPI: 0 = bias -> qkv planes (Q scaled hi+lo; K/V hi only); 1 = bias+gelu -> planes;
//      3 = raw split-K partial -> fp32 slice buffer
template <int EPI>
__global__ __launch_bounds__(256, 2) void mgemm(
    const __nv_bfloat16* __restrict__ Ah_g, const __nv_bfloat16* __restrict__ Al_g,
    const __nv_bfloat16* __restrict__ Bh_g, const __nv_bfloat16* __restrict__ Bl_g,
    const float* __restrict__ b0, const float* __restrict__ b1, const float* __restrict__ b2,
    float* __restrict__ C0,
    __nv_bfloat16* __restrict__ P0h, __nv_bfloat16* __restrict__ P0l,
    __nv_bfloat16* __restrict__ P1h,
    __nv_bfloat16* __restrict__ P2h,
    int Nst, int K, int Kst) {
    extern __shared__ char smem[];
    uint32_t sb = smem_u32(smem);
    int tid = threadIdx.x;
    int lane = tid & 31;
    int wid = tid >> 5;
    int wm = wid >> 2;
    int wn = wid & 3;
    int m0 = blockIdx.y * BMT;
    int n0 = blockIdx.x * BN;
    int z = (EPI == 3) ? blockIdx.z : 0;
    long long zoff = (long long)z * K * 2;

    const char* Ahb = (const char*)Ah_g + ((long long)m0 * Kst) * 2 + zoff;
    const char* Alb = (const char*)Al_g + ((long long)m0 * Kst) * 2 + zoff;
    const char* Bhb = (const char*)Bh_g + ((long long)n0 * Kst) * 2 + zoff;
    const char* Blb = (const char*)Bl_g + ((long long)n0 * Kst) * 2 + zoff;
    const long long rowstride = (long long)Kst * 2;

    float acc[2][4][4];
#pragma unroll
    for (int i = 0; i < 2; i++)
#pragma unroll
        for (int j = 0; j < 4; j++)
#pragma unroll
            for (int r = 0; r < 4; r++) acc[i][j][r] = 0.0f;

    const int lrow = lane & 15;
    const int lhalf = lane >> 4;
    const int T = K / BK;

    int rowa[2], cba[2];
    uint32_t offa[2];
#pragma unroll
    for (int i = 0; i < 2; i++) {
        int ck = i * 256 + tid;
        rowa[i] = ck >> 3;
        cba[i] = (ck & 7) * 16;
        offa[i] = SWZ128((uint32_t)(rowa[i] * 128 + cba[i]));
    }
    int rowb[4], cbb[4];
    uint32_t offb[4];
#pragma unroll
    for (int i = 0; i < 4; i++) {
        int ck = i * 256 + tid;
        rowb[i] = ck >> 3;
        cbb[i] = (ck & 7) * 16;
        offb[i] = SWZ128((uint32_t)(rowb[i] * 128 + cbb[i]));
    }

#define LOAD_STAGE(t, s)                                                \
    do {                                                                \
        uint32_t stg = sb + (s) * GSTG;                                 \
        long long kb = (long long)(t) * (BK * 2);                       \
        _Pragma("unroll") for (int i = 0; i < 2; i++) {                 \
            long long src = rowa[i] * rowstride + kb + cba[i];          \
            CP_ASYNC16(stg + offa[i], Ahb + src);                       \
            CP_ASYNC16(stg + GOFF_AL + offa[i], Alb + src);             \
        }                                                               \
        _Pragma("unroll") for (int i = 0; i < 4; i++) {                 \
            long long src = rowb[i] * rowstride + kb + cbb[i];          \
            CP_ASYNC16(stg + GOFF_BH + offb[i], Bhb + src);             \
            CP_ASYNC16(stg + GOFF_BL + offb[i], Blb + src);             \
        }                                                               \
    } while (0)

    LOAD_STAGE(0, 0);
    CP_COMMIT;

    for (int t = 0; t < T; t++) {
        CP_WAIT(0);
        __syncthreads();
        if (t + 1 < T) {
            LOAD_STAGE(t + 1, (t + 1) & 1);
            CP_COMMIT;
        }
        uint32_t stg = sb + (t & 1) * GSTG;
#pragma unroll
        for (int ks = 0; ks < 4; ks++) {
            int kb = ks * 32 + lhalf * 16;
            uint32_t ah[2][4], al[2][4], bh[2][4], bl[2][4];
#pragma unroll
            for (int mt = 0; mt < 2; mt++) {
                int r = wm * 32 + mt * 16 + lrow;
                uint32_t off = SWZ128((uint32_t)(r * 128 + kb));
                LDSM_X4(ah[mt], stg + off);
                LDSM_X4(al[mt], stg + GOFF_AL + off);
            }
#pragma unroll
            for (int g2 = 0; g2 < 2; g2++) {
                int r = wn * 32 + g2 * 16 + lrow;
                uint32_t off = SWZ128((uint32_t)(r * 128 + kb));
                LDSM_X4(bh[g2], stg + GOFF_BH + off);
                LDSM_X4(bl[g2], stg + GOFF_BL + off);
            }
#pragma unroll
            for (int mt = 0; mt < 2; mt++)
#pragma unroll
                for (int j = 0; j < 4; j++) {
                    uint32_t b0h = bh[j >> 1][j & 1], b1h = bh[j >> 1][(j & 1) + 2];
                    uint32_t b0l = bl[j >> 1][j & 1], b1l = bl[j >> 1][(j & 1) + 2];
                    MMA_BF16(acc[mt][j], ah[mt], b0h, b1h);
                    MMA_BF16(acc[mt][j], ah[mt], b0l, b1l);
                    MMA_BF16(acc[mt][j], al[mt], b0h, b1h);
                }
        }
    }

    // ---- epilogue ----
    int g = lane >> 2;
    int tig = lane & 3;

    const float* bias = b0;
    __nv_bfloat16 *Poh = P0h, *Pol = P0l;
    float* Cp = C0;
    int ncol0 = n0;
    int mat = 0;
    if (EPI == 0) {
        mat = n0 / 768;
        ncol0 = n0 % 768;
        bias = (mat == 0) ? b0 : ((mat == 1) ? b1 : b2);
        Poh = (mat == 0) ? P0h : ((mat == 1) ? P1h : P2h);
        Pol = P0l;  // only used when mat == 0
    }
    if (EPI == 3) Cp = C0 + (long long)z * S * 768;
    const int ost = (EPI == 0 || EPI == 3) ? 768 : Nst;

#pragma unroll
    for (int mt = 0; mt < 2; mt++) {
#pragma unroll
        for (int j = 0; j < 4; j++) {
            int colrel = ncol0 + wn * 32 + j * 8 + tig * 2;
            float bia0 = (EPI == 3) ? 0.0f : bias[colrel];
            float bia1 = (EPI == 3) ? 0.0f : bias[colrel + 1];
#pragma unroll
            for (int half = 0; half < 2; half++) {
                int row = m0 + wm * 32 + mt * 16 + g + half * 8;
                long long rb = (long long)row * ost + colrel;
                float u0 = acc[mt][j][half * 2 + 0] + bia0;
                float u1 = acc[mt][j][half * 2 + 1] + bia1;
                if (EPI == 0) {
                    if (mat == 0) {
                        u0 *= QSC;
                        u1 *= QSC;
                        split_pair(u0, u1, Poh + rb, Pol + rb);
                    } else {
                        pack_hi(u0, u1, Poh + rb);  // K/V: hi plane only
                    }
                } else if (EPI == 1) {
                    u0 = 0.5f * u0 * (1.0f + erff(u0 * 0.70710678118654752f));
                    u1 = 0.5f * u1 * (1.0f + erff(u1 * 0.70710678118654752f));
                    split_pair(u0, u1, Poh + rb, Pol + rb);
                } else {
                    *(float2*)(&Cp[rb]) = make_float2(u0, u1);
                }
            }
        }
    }
}

// ======== tensor-core sliding-window attention (bf16 K/V, bf16x2 Q/P) ========
// Q planes 32KB; 2 stages x {KH 8KB, VH 8KB} = 32KB; total 64KB smem.
#define AQR 128
#define AKT 64
#define ANT 10
#define AST_BASE 32768
#define ASTG 16384
#define ATT_SMEM (32768 + 2 * ASTG)

__global__ __launch_bounds__(256, 2) void attn_tc(
    const __nv_bfloat16* __restrict__ qh, const __nv_bfloat16* __restrict__ ql,
    const __nv_bfloat16* __restrict__ kh, const __nv_bfloat16* __restrict__ vh,
    __nv_bfloat16* __restrict__ aoh, __nv_bfloat16* __restrict__ aol) {
    extern __shared__ char smem[];
    uint32_t sb = smem_u32(smem);
    int tid = threadIdx.x;
    int lane = tid & 31;
    int wid = tid >> 5;
    int c = blockIdx.x;
    int h = blockIdx.y;
    const int q0g = c * AQR;
    const int cbase = q0g - W;
    const int lrow = lane & 15;
    const int lhalf = lane >> 4;
    const int wr0 = wid * 16;

#pragma unroll
    for (int i = 0; i < 4; i++) {
        int id = i * 256 + tid;
        int row = id >> 3;
        int cb = (id & 7) * 16;
        long long gsrc = ((long long)(q0g + row) * D + h * DH) * 2 + cb;
        uint32_t dst = sb + SWZ128((uint32_t)(row * 128 + cb));
        CP_ASYNC16(dst, (const char*)qh + gsrc);
        CP_ASYNC16(dst + 16384, (const char*)ql + gsrc);
    }

#define ATT_LOAD(kt, s)                                                               \
    do {                                                                              \
        uint32_t stb = sb + AST_BASE + (s) * ASTG;                                    \
        _Pragma("unroll") for (int pl_ = 0; pl_ < 2; pl_++) {                         \
            const char* gp = (pl_ == 0) ? (const char*)kh : (const char*)vh;          \
            _Pragma("unroll") for (int j_ = 0; j_ < 2; j_++) {                        \
                int rem = j_ * 256 + tid;                                             \
                int row = rem >> 3;                                                   \
                int cb = (rem & 7) * 16;                                              \
                int kg = cbase + (kt) * AKT + row;                                    \
                int ok = (kg >= 0 && kg < S);                                         \
                int kgc = ok ? kg : 0;                                                \
                long long gsrc = ((long long)kgc * D + h * DH) * 2 + cb;              \
                CP_ASYNC16Z(stb + pl_ * 8192 + SWZ128((uint32_t)(row * 128 + cb)),    \
                            gp + gsrc, ok ? 16 : 0);                                  \
            }                                                                         \
        }                                                                             \
    } while (0)

    ATT_LOAD(0, 0);
    CP_COMMIT;

    float acc[8][4];
#pragma unroll
    for (int nf = 0; nf < 8; nf++)
#pragma unroll
        for (int e = 0; e < 4; e++) acc[nf][e] = 0.0f;
    float mrow[2] = {-1e30f, -1e30f};
    float lrowv[2] = {0.0f, 0.0f};

    for (int kt = 0; kt < ANT; kt++) {
        CP_WAIT(0);
        __syncthreads();
        if (kt + 1 < ANT) {
            ATT_LOAD(kt + 1, (kt + 1) & 1);
            CP_COMMIT;
        }
        int jg0 = kt * AKT;
        bool active = (jg0 + AKT > wr0) && (jg0 <= wr0 + 15 + 2 * W);
        if (active) {
            uint32_t stb = sb + AST_BASE + (kt & 1) * ASTG;
            uint32_t KH = stb, VH = stb + 8192;

            float sf[8][4];
#pragma unroll
            for (int nf = 0; nf < 8; nf++)
#pragma unroll
                for (int e = 0; e < 4; e++) sf[nf][e] = 0.0f;

#pragma unroll
            for (int ks = 0; ks < 4; ks++) {
                int kb = ks * 32 + lhalf * 16;
                uint32_t qhf[4], qlf[4];
                uint32_t qoff = SWZ128((uint32_t)((wr0 + lrow) * 128 + kb));
                LDSM_X4(qhf, sb + qoff);
                LDSM_X4(qlf, sb + 16384 + qoff);
#pragma unroll
                for (int nf2 = 0; nf2 < 4; nf2++) {
                    uint32_t khf[4];
                    uint32_t off = SWZ128((uint32_t)((nf2 * 16 + lrow) * 128 + kb));
                    LDSM_X4(khf, KH + off);
#pragma unroll
                    for (int hf = 0; hf < 2; hf++) {
                        int nf = nf2 * 2 + hf;
                        uint32_t b0h = khf[hf], b1h = khf[hf + 2];
                        MMA_BF16(sf[nf], qhf, b0h, b1h);
                        MMA_BF16(sf[nf], qlf, b0h, b1h);
                    }
                }
            }

            int rA = wr0 + (lane >> 2);
            int rB = rA + 8;
#pragma unroll
            for (int nf = 0; nf < 8; nf++)
#pragma unroll
                for (int e = 0; e < 4; e++) {
                    int col = jg0 + nf * 8 + (lane & 3) * 2 + (e & 1);
                    int row = (e < 2) ? rA : rB;
                    int kg = cbase + col;
                    bool ok = (col >= row) && (col <= row + 2 * W) && (kg >= 0) && (kg < S);
                    if (!ok) sf[nf][e] = -1e30f;
                }
            float mA = -1e30f, mB = -1e30f;
#pragma unroll
            for (int nf = 0; nf < 8; nf++) {
                mA = fmaxf(mA, fmaxf(sf[nf][0], sf[nf][1]));
                mB = fmaxf(mB, fmaxf(sf[nf][2], sf[nf][3]));
            }
            mA = fmaxf(mA, __shfl_xor_sync(0xffffffffu, mA, 1));
            mA = fmaxf(mA, __shfl_xor_sync(0xffffffffu, mA, 2));
            mB = fmaxf(mB, __shfl_xor_sync(0xffffffffu, mB, 1));
            mB = fmaxf(mB, __shfl_xor_sync(0xffffffffu, mB, 2));
            float mnA = fmaxf(mrow[0], mA);
            float mnB = fmaxf(mrow[1], mB);
            float scA = exp2f(mrow[0] - mnA);
            float scB = exp2f(mrow[1] - mnB);
            float sumA = 0.0f, sumB = 0.0f;
#pragma unroll
            for (int nf = 0; nf < 8; nf++) {
                float p0 = exp2f(sf[nf][0] - mnA);
                float p1 = exp2f(sf[nf][1] - mnA);
                float p2 = exp2f(sf[nf][2] - mnB);
                float p3 = exp2f(sf[nf][3] - mnB);
                sf[nf][0] = p0;
                sf[nf][1] = p1;
                sf[nf][2] = p2;
                sf[nf][3] = p3;
                sumA += p0 + p1;
                sumB += p2 + p3;
            }
            sumA += __shfl_xor_sync(0xffffffffu, sumA, 1);
            sumA += __shfl_xor_sync(0xffffffffu, sumA, 2);
            sumB += __shfl_xor_sync(0xffffffffu, sumB, 1);
            sumB += __shfl_xor_sync(0xffffffffu, sumB, 2);
            lrowv[0] = lrowv[0] * scA + sumA;
            lrowv[1] = lrowv[1] * scB + sumB;
#pragma unroll
            for (int of = 0; of < 8; of++) {
                acc[of][0] *= scA;
                acc[of][1] *= scA;
                acc[of][2] *= scB;
                acc[of][3] *= scB;
            }
            mrow[0] = mnA;
            mrow[1] = mnB;

#pragma unroll
            for (int ks2 = 0; ks2 < 4; ks2++) {
                const float* s0 = sf[2 * ks2];
                const float* s1 = sf[2 * ks2 + 1];
                uint32_t pah[4], pal[4];
                pack_hl(s0[0], s0[1], pah[0], pal[0]);
                pack_hl(s0[2], s0[3], pah[1], pal[1]);
                pack_hl(s1[0], s1[1], pah[2], pal[2]);
                pack_hl(s1[2], s1[3], pah[3], pal[3]);
#pragma unroll
                for (int vf2 = 0; vf2 < 4; vf2++) {
                    uint32_t vhf[4];
                    uint32_t off =
                        SWZ128((uint32_t)((ks2 * 16 + lrow) * 128 + vf2 * 32 + lhalf * 16));
                    LDSM_X4_T(vhf, VH + off);
#pragma unroll
                    for (int hf = 0; hf < 2; hf++) {
                        int nf = vf2 * 2 + hf;
                        uint32_t b0h = vhf[hf * 2], b1h = vhf[hf * 2 + 1];
                        MMA_BF16(acc[nf], pah, b0h, b1h);
                        MMA_BF16(acc[nf], pal, b0h, b1h);
                    }
                }
            }
        }
    }

    {
        float invA = 1.0f / lrowv[0];
        float invB = 1.0f / lrowv[1];
        int rA = wr0 + (lane >> 2);
        long long baseA = (long long)(q0g + rA) * D + h * DH;
        long long baseB = baseA + 8LL * D;
#pragma unroll
        for (int nf = 0; nf < 8; nf++) {
            int col = nf * 8 + (lane & 3) * 2;
            split_pair(acc[nf][0] * invA, acc[nf][1] * invA, aoh + baseA + col,
                       aol + baseA + col);
            split_pair(acc[nf][2] * invB, acc[nf][3] * invB, aoh + baseB + col,
                       aol + baseB + col);
        }
    }
}

__global__ void head_kernel(const float* __restrict__ hrow, const float* __restrict__ w,
                            const float* __restrict__ b, float* __restrict__ out) {
    int o = threadIdx.x;
    float acc = b[o];
    for (int d = 0; d < D; d++) acc += hrow[d] * w[d * OUT + o];
    out[o] = acc;
}

// ================= launch =================
extern "C" void kernel_launch(void* const* d_in, const int* in_sizes, int n_in,
                              void* d_out, int out_size) {
    (void)in_sizes; (void)n_in; (void)out_size;
    const int* x = (const int*)d_in[0];
    const float* word_emb = (const float*)d_in[1];
    const float* pos_emb = (const float*)d_in[2];
    const float* tt_emb = (const float*)d_in[3];
    const float* elg = (const float*)d_in[4];
    const float* elb = (const float*)d_in[5];
    const float* Wq = (const float*)d_in[6];
    const float* bq = (const float*)d_in[7];
    const float* Wk = (const float*)d_in[8];
    const float* bk = (const float*)d_in[9];
    const float* Wv = (const float*)d_in[10];
    const float* bv = (const float*)d_in[11];
    const float* Wo = (const float*)d_in[12];
    const float* bo = (const float*)d_in[13];
    const float* g1 = (const float*)d_in[14];
    const float* b1 = (const float*)d_in[15];
    const float* Wi = (const float*)d_in[16];
    const float* bi = (const float*)d_in[17];
    const float* Wd = (const float*)d_in[18];
    const float* bd = (const float*)d_in[19];
    const float* g2 = (const float*)d_in[20];
    const float* b2 = (const float*)d_in[21];
    const float* ow = (const float*)d_in[22];
    const float* ob = (const float*)d_in[23];
    float* out = (float*)d_out;

    float *h, *part;
    __nv_bfloat16 *qh, *ql, *kh, *vh, *hh, *hl, *ah, *al, *fh, *fl, *wTh, *wTl;
    cudaGetSymbolAddress((void**)&h, g_h);
    cudaGetSymbolAddress((void**)&part, g_part);
    cudaGetSymbolAddress((void**)&qh, g_qh);
    cudaGetSymbolAddress((void**)&ql, g_ql);
    cudaGetSymbolAddress((void**)&kh, g_kh);
    cudaGetSymbolAddress((void**)&vh, g_vh);
    cudaGetSymbolAddress((void**)&hh, g_hh);
    cudaGetSymbolAddress((void**)&hl, g_hl);
    cudaGetSymbolAddress((void**)&ah, g_ah);
    cudaGetSymbolAddress((void**)&al, g_al);
    cudaGetSymbolAddress((void**)&fh, g_fh);
    cudaGetSymbolAddress((void**)&fl, g_fl);
    cudaGetSymbolAddress((void**)&wTh, g_wTh);
    cudaGetSymbolAddress((void**)&wTl, g_wTl);

    cudaFuncSetAttribute(mgemm<0>, cudaFuncAttributeMaxDynamicSharedMemorySize, SMEM_G);
    cudaFuncSetAttribute(mgemm<1>, cudaFuncAttributeMaxDynamicSharedMemorySize, SMEM_G);
    cudaFuncSetAttribute(mgemm<3>, cudaFuncAttributeMaxDynamicSharedMemorySize, SMEM_G);
    cudaFuncSetAttribute(attn_tc, cudaFuncAttributeMaxDynamicSharedMemorySize, ATT_SMEM);

    dim3 tb(32, 8);
    tsp_dd<<<dim3(D / 32, D / 32, 4 * L), tb>>>(Wq, Wk, Wv, Wo, wTh, wTl);
    emb_kernel<<<S, 256>>>(x, word_emb, pos_emb, tt_emb, part);  // reuse part as temp
    ln_kernel<<<S, 256>>>(part, elg, elb, h, hh, hl);

    dim3 gqkv(2304 / BN, S / BMT);     // 18 x 64
    dim3 gwo(768 / BN, S / BMT, 2);    // 6 x 64 x 2 (split-K=2)
    dim3 gff1(FF / BN, S / BMT);       // 24 x 64
    dim3 gff2(768 / BN, S / BMT, 4);   // 6 x 64 x 4 (split-K=4)
    dim3 gattn(S / AQR, H);            // 32 x 12

    for (int l = 0; l < L; l++) {
        long long lb = (long long)l * WT_PER_LAYER;

        mgemm<0><<<gqkv, 256, SMEM_G>>>(hh, hl, wTh + lb + OQKV, wTl + lb + OQKV,
                                        bq + l * D, bk + l * D, bv + l * D,
                                        nullptr, qh, ql, kh, vh, 768, D, D);

        if (l == 0) {
            tsp_wi<<<dim3(FF / 32, D / 32, L), tb>>>(Wi, wTh, wTl);
            tsp_wd<<<dim3(D / 32, FF / 32, L), tb>>>(Wd, wTh, wTl);
        }

        attn_tc<<<gattn, 256, ATT_SMEM>>>(qh, ql, kh, vh, ah, al);

        // Wo: split-K=2 partials, reduce fused into LN1
        mgemm<3><<<gwo, 256, SMEM_G>>>(ah, al, wTh + lb + OO, wTl + lb + OO,
                                       nullptr, nullptr, nullptr, part,
                                       nullptr, nullptr, nullptr, nullptr,
                                       768, 384, D);
        ln_red_kernel<2><<<S, 256>>>(part, bo + l * D, h, g1 + l * D, b1 + l * D, h, hh, hl);

        mgemm<1><<<gff1, 256, SMEM_G>>>(hh, hl, wTh + lb + OI, wTl + lb + OI,
                                        bi + l * FF, nullptr, nullptr, nullptr,
                                        fh, fl, nullptr, nullptr, FF, D, D);

        // FF2: split-K=4 partials, reduce fused into LN2
        mgemm<3><<<gff2, 256, SMEM_G>>>(fh, fl, wTh + lb + OD, wTl + lb + OD,
                                        nullptr, nullptr, nullptr, part,
                                        nullptr, nullptr, nullptr, nullptr,
                                        768, 768, FF);
        ln_red_kernel<4><<<S, 256>>>(part, bd + l * D, h, g2 + l * D, b2 + l * D, h, hh, hl);
    }

    head_kernel<<<1, 256>>>(h, ow, ob, out);
}